// round 9
// baseline (speedup 1.0000x reference)
#include <cuda_runtime.h>
#include <cuda_bf16.h>
#include <cuda_pipeline.h>
#include <mma.h>
#include <math.h>
#include <cstdint>

using namespace nvcuda;

// ---------------- problem constants ----------------
#define BB 4
#define SS 2048
#define DD 768
#define HH 12
#define HDD 64
#define RA 32
#define RF 512
#define DFF 3072
#define ROWS (BB*SS)          // 8192

// ---------------- GEMM tile constants ----------------
#define BK 32
#define LDAs 40               // bf16 elems (80B rows, 16B aligned)
#define LDBs 136              // bf16 elems (272B rows)
#define A_TILE (128*LDAs)     // 5120
#define B_TILE (BK*LDBs)      // 4352
#define STAGE (2*A_TILE + 2*B_TILE)   // 18944 bf16
#define GEMM_SMEM (2*STAGE*2)         // 75776 bytes
#define LDC 132               // Csm floats: 128*132*4 = 67584 <= 75776

typedef __nv_bfloat16 bf16;

// ---------------- scratch ----------------
__device__ bf16  g_hh [ROWS*DD];
__device__ bf16  g_hl [ROWS*DD];
__device__ bf16  g_weffh[3*DD*DD];     // [which][k][n]
__device__ bf16  g_weffl[3*DD*DD];
__device__ bf16  g_woth[DD*DD];        // Wo^T [k][n]
__device__ bf16  g_wotl[DD*DD];
__device__ bf16  g_uih[DD*RF],  g_uil[DD*RF];
__device__ bf16  g_vih[RF*2*DFF], g_vil[RF*2*DFF];    // column-interleaved (g1,g2 pairs)
__device__ bf16  g_uoh[DFF*RF], g_uol[DFF*RF];
__device__ bf16  g_voh[RF*DD],  g_vol[RF*DD];
__device__ bf16  g_qh [ROWS*DD], g_ql[ROWS*DD];   // [B,H,S,HD] post-rope, q scaled
__device__ bf16  g_kh [ROWS*DD], g_kl[ROWS*DD];
__device__ bf16  g_vh [ROWS*DD], g_vl[ROWS*DD];
__device__ bf16  g_oh [ROWS*DD], g_ol[ROWS*DD];
__device__ float g_x1 [ROWS*DD];
__device__ bf16  g_h2h[ROWS*DD], g_h2l[ROWS*DD];
__device__ bf16  g_t1h[ROWS*RF], g_t1l[ROWS*RF];
__device__ bf16  g_gh [ROWS*DFF], g_gl[ROWS*DFF];
__device__ bf16  g_t2h[ROWS*RF], g_t2l[ROWS*RF];

__device__ __forceinline__ void bsplit(float a, bf16& h, bf16& l) {
    h = __float2bfloat16(a);
    l = __float2bfloat16(a - __bfloat162float(h));
}
__device__ __forceinline__ unsigned pack2(bf16 a, bf16 b) {
    __nv_bfloat162 t(a, b);
    return *(unsigned*)&t;
}
__device__ __forceinline__ float gelu_t(float x) {
    float t = 0.7978845608028654f * (x + 0.044715f * x * x * x);
    return 0.5f * x * (1.0f + tanhf(t));
}

// ---------------- layernorm -> bf16 hi/lo (warp-shuffle reduction) ----------------
__global__ __launch_bounds__(256) void ln_split(const float* __restrict__ x,
                                                const float* __restrict__ w,
                                                const float* __restrict__ b,
                                                bf16* __restrict__ oh,
                                                bf16* __restrict__ ol) {
    int row = blockIdx.x;
    const float* xr = x + (size_t)row * DD;
    float vals[3];
    float s = 0.f, s2 = 0.f;
    int tid = threadIdx.x;
#pragma unroll
    for (int i = 0; i < 3; i++) {
        float v = xr[tid + i * 256];
        vals[i] = v; s += v; s2 += v * v;
    }
#pragma unroll
    for (int off = 16; off > 0; off >>= 1) {
        s  += __shfl_xor_sync(0xffffffffu, s,  off);
        s2 += __shfl_xor_sync(0xffffffffu, s2, off);
    }
    __shared__ float sh[8], sh2[8];
    int warp = tid >> 5, lane = tid & 31;
    if (lane == 0) { sh[warp] = s; sh2[warp] = s2; }
    __syncthreads();
    float ts = 0.f, ts2 = 0.f;
#pragma unroll
    for (int i = 0; i < 8; i++) { ts += sh[i]; ts2 += sh2[i]; }
    float mean = ts * (1.0f / DD);
    float var  = ts2 * (1.0f / DD) - mean * mean;
    float rstd = rsqrtf(var + 1e-6f);
#pragma unroll
    for (int i = 0; i < 3; i++) {
        int c = tid + i * 256;
        float y = (vals[i] - mean) * rstd * w[c] + b[c];
        bsplit(y, oh[(size_t)row * DD + c], ol[(size_t)row * DD + c]);
    }
}

// ---------------- effective weight -> hi/lo ([k][n]) ----------------
__global__ __launch_bounds__(256) void weff_kernel(const float* __restrict__ Uq, const float* __restrict__ Vq,
                                                   const float* __restrict__ Uk, const float* __restrict__ Vk,
                                                   const float* __restrict__ Uv, const float* __restrict__ Vv,
                                                   bf16* __restrict__ wh, bf16* __restrict__ wl) {
    int idx = blockIdx.x * 256 + threadIdx.x;
    if (idx >= 3 * DD * DD) return;
    int which = idx / (DD * DD);
    int rem = idx % (DD * DD);
    int d = rem / DD, j = rem % DD;
    int hh = j >> 6, e = j & 63;
    const float* U = (which == 0) ? Uq : (which == 1) ? Uk : Uv;
    const float* V = (which == 0) ? Vq : (which == 1) ? Vk : Vv;
    const float* Uhd = U + ((size_t)hh * DD + d) * RA;
    const float* Vh  = V + (size_t)hh * RA * HDD + e;
    float acc = 0.f;
#pragma unroll
    for (int r = 0; r < RA; r++) acc += Uhd[r] * Vh[r * HDD];
    bsplit(acc, wh[idx], wl[idx]);
}

// ---------------- splits ----------------
__global__ __launch_bounds__(256) void split_kernel(const float* __restrict__ in,
                                                    bf16* __restrict__ oh, bf16* __restrict__ ol, int n) {
    int i = blockIdx.x * 256 + threadIdx.x;
    if (i < n) bsplit(in[i], oh[i], ol[i]);
}
__global__ __launch_bounds__(256) void wo_t_split(const float* __restrict__ Wo,
                                                  bf16* __restrict__ oh, bf16* __restrict__ ol) {
    int idx = blockIdx.x * 256 + threadIdx.x;
    if (idx >= DD * DD) return;
    int k = idx / DD, n = idx % DD;
    bsplit(Wo[(size_t)n * DD + k], oh[idx], ol[idx]);
}
// Vi [RF, 2*DFF] -> interleaved columns
__global__ __launch_bounds__(256) void vi_perm_split(const float* __restrict__ Vi,
                                                     bf16* __restrict__ oh, bf16* __restrict__ ol) {
    int idx = blockIdx.x * 256 + threadIdx.x;
    if (idx >= RF * 2 * DFF) return;
    int k = idx / (2 * DFF), n = idx % (2 * DFF);
    int j = n >> 1;
    int srcn = (n & 1) ? (DFF + j) : j;
    bsplit(Vi[(size_t)k * (2 * DFF) + srcn], oh[idx], ol[idx]);
}

// ---------------- bf16x3 split tensor-core GEMM (wmma, term-major issue) ----------------
template<int OUTMODE>
__global__ __launch_bounds__(256, 2) void gemm_bf3(
    const bf16* __restrict__ Agh, const bf16* __restrict__ Agl,
    const bf16* __restrict__ Bgh, const bf16* __restrict__ Bgl,
    const float* __restrict__ bias, const float* __restrict__ res,
    const float* __restrict__ cosT, const float* __restrict__ sinT, float scale,
    float* __restrict__ C, bf16* __restrict__ Ch, bf16* __restrict__ Cl,
    int M, int N, int K)
{
    extern __shared__ __align__(16) char smraw[];
    bf16* smb = (bf16*)smraw;
    int tid = threadIdx.x;
    int wid = tid >> 5;
    int warp_m = wid >> 2;   // 0..1
    int warp_n = wid & 3;    // 0..3
    int m0 = blockIdx.y * 128, n0 = blockIdx.x * 128;

    auto issue = [&](int c, int st) {
        int k0 = c * BK;
        bf16* sAh = smb + st * STAGE;
        bf16* sAl = sAh + A_TILE;
        bf16* sBh = sAl + A_TILE;
        bf16* sBl = sBh + B_TILE;
#pragma unroll
        for (int i = 0; i < 2; i++) {
            int t = tid + i * 256;
            int ar = t >> 2;
            int ac = (t & 3) * 8;
            size_t ag = (size_t)(m0 + ar) * K + k0 + ac;
            __pipeline_memcpy_async(&sAh[ar * LDAs + ac], &Agh[ag], 16);
            __pipeline_memcpy_async(&sAl[ar * LDAs + ac], &Agl[ag], 16);
            int br = t >> 4;
            int bc = (t & 15) * 8;
            size_t bg = (size_t)(k0 + br) * N + n0 + bc;
            __pipeline_memcpy_async(&sBh[br * LDBs + bc], &Bgh[bg], 16);
            __pipeline_memcpy_async(&sBl[br * LDBs + bc], &Bgl[bg], 16);
        }
    };

    wmma::fragment<wmma::accumulator, 16, 16, 16, float> cf[4][2];
#pragma unroll
    for (int i = 0; i < 4; i++)
#pragma unroll
        for (int j = 0; j < 2; j++) wmma::fill_fragment(cf[i][j], 0.0f);

    int nch = K / BK;
    issue(0, 0); __pipeline_commit();
    if (nch > 1) issue(1, 1);
    __pipeline_commit();

    for (int c = 0; c < nch; c++) {
        __pipeline_wait_prior(1);
        __syncthreads();
        int st = c & 1;
        bf16* sAh = smb + st * STAGE;
        bf16* sAl = sAh + A_TILE;
        bf16* sBh = sAl + A_TILE;
        bf16* sBl = sBh + B_TILE;
#pragma unroll
        for (int ks = 0; ks < 2; ks++) {
            wmma::fragment<wmma::matrix_b, 16, 16, 16, bf16, wmma::row_major> bh[2], bl[2];
            wmma::fragment<wmma::matrix_a, 16, 16, 16, bf16, wmma::row_major> ah[4], al[4];
#pragma unroll
            for (int j = 0; j < 2; j++) {
                wmma::load_matrix_sync(bh[j], &sBh[(ks * 16) * LDBs + warp_n * 32 + j * 16], LDBs);
                wmma::load_matrix_sync(bl[j], &sBl[(ks * 16) * LDBs + warp_n * 32 + j * 16], LDBs);
            }
#pragma unroll
            for (int i = 0; i < 4; i++) {
                wmma::load_matrix_sync(ah[i], &sAh[(warp_m * 64 + i * 16) * LDAs + ks * 16], LDAs);
                wmma::load_matrix_sync(al[i], &sAl[(warp_m * 64 + i * 16) * LDAs + ks * 16], LDAs);
            }
            // term-major: consecutive MMAs hit different accumulators
#pragma unroll
            for (int i = 0; i < 4; i++)
#pragma unroll
                for (int j = 0; j < 2; j++)
                    wmma::mma_sync(cf[i][j], ah[i], bh[j], cf[i][j]);
#pragma unroll
            for (int i = 0; i < 4; i++)
#pragma unroll
                for (int j = 0; j < 2; j++)
                    wmma::mma_sync(cf[i][j], ah[i], bl[j], cf[i][j]);
#pragma unroll
            for (int i = 0; i < 4; i++)
#pragma unroll
                for (int j = 0; j < 2; j++)
                    wmma::mma_sync(cf[i][j], al[i], bh[j], cf[i][j]);
        }
        __syncthreads();
        if (c + 2 < nch) issue(c + 2, st);
        __pipeline_commit();
    }

    // ---- epilogue ----
    float* Csm = (float*)smraw;
#pragma unroll
    for (int i = 0; i < 4; i++)
#pragma unroll
        for (int j = 0; j < 2; j++)
            wmma::store_matrix_sync(&Csm[(warp_m * 64 + i * 16) * LDC + warp_n * 32 + j * 16],
                                    cf[i][j], LDC, wmma::mem_row_major);
    __syncthreads();

#pragma unroll
    for (int it = 0; it < 16; it++) {
        int idx = tid + it * 256;
        int r = idx >> 5;
        int c4 = (idx & 31) << 2;
        float4 v = *(const float4*)&Csm[r * LDC + c4];
        int m = m0 + r, n = n0 + c4;
        if (OUTMODE <= 3) {
            if (bias) {
                float4 bb = *(const float4*)&bias[n];
                v.x += bb.x; v.y += bb.y; v.z += bb.z; v.w += bb.w;
            }
            if (res) {
                float4 rr = *(const float4*)&res[(size_t)m * N + n];
                v.x += rr.x; v.y += rr.y; v.z += rr.z; v.w += rr.w;
            }
        }
        if (OUTMODE == 0) {
            *(float4*)&C[(size_t)m * N + n] = v;
        } else if (OUTMODE == 2) {
            bf16 hv[4], lv[4];
            bsplit(v.x, hv[0], lv[0]); bsplit(v.y, hv[1], lv[1]);
            bsplit(v.z, hv[2], lv[2]); bsplit(v.w, hv[3], lv[3]);
            *(uint2*)&Ch[(size_t)m * N + n] = *(uint2*)hv;
            *(uint2*)&Cl[(size_t)m * N + n] = *(uint2*)lv;
        } else if (OUTMODE == 3) {
            int b = m >> 11, s = m & 2047, head = n >> 6, e = n & 63;
            size_t o = (((size_t)b * HH + head) * SS + s) * HDD + e;
            bf16 hv[4], lv[4];
            bsplit(v.x, hv[0], lv[0]); bsplit(v.y, hv[1], lv[1]);
            bsplit(v.z, hv[2], lv[2]); bsplit(v.w, hv[3], lv[3]);
            *(uint2*)&Ch[o] = *(uint2*)hv;
            *(uint2*)&Cl[o] = *(uint2*)lv;
        } else if (OUTMODE == 4) {
            int j0 = n >> 1;
            float g1a = v.x + bias[j0];
            float g2a = v.y + bias[DFF + j0];
            float g1b = v.z + bias[j0 + 1];
            float g2b = v.w + bias[DFF + j0 + 1];
            float ga = gelu_t(g1a) * g2a;
            float gb = gelu_t(g1b) * g2b;
            bf16 h0, l0, h1, l1;
            bsplit(ga, h0, l0); bsplit(gb, h1, l1);
            size_t o = (size_t)m * DFF + j0;
            *(unsigned*)&Ch[o] = pack2(h0, h1);
            *(unsigned*)&Cl[o] = pack2(l0, l1);
        } else {  // OUTMODE == 5: rope + scale + scatter split
            int e = n & 63;
            float4 p = *(const float4*)&Csm[r * LDC + (c4 ^ 32)];
            {
                float4 bb = *(const float4*)&bias[n];
                v.x += bb.x; v.y += bb.y; v.z += bb.z; v.w += bb.w;
                float4 pb = *(const float4*)&bias[n ^ 32];
                p.x += pb.x; p.y += pb.y; p.z += pb.z; p.w += pb.w;
            }
            int s = m & 2047;
            float4 cs = *(const float4*)&cosT[s * HDD + e];
            float4 sn = *(const float4*)&sinT[s * HDD + e];
            float4 o4;
            if (e < 32) {
                o4.x = v.x * cs.x - p.x * sn.x; o4.y = v.y * cs.y - p.y * sn.y;
                o4.z = v.z * cs.z - p.z * sn.z; o4.w = v.w * cs.w - p.w * sn.w;
            } else {
                o4.x = v.x * cs.x + p.x * sn.x; o4.y = v.y * cs.y + p.y * sn.y;
                o4.z = v.z * cs.z + p.z * sn.z; o4.w = v.w * cs.w + p.w * sn.w;
            }
            o4.x *= scale; o4.y *= scale; o4.z *= scale; o4.w *= scale;
            int b = m >> 11, head = n >> 6;
            size_t o = (((size_t)b * HH + head) * SS + s) * HDD + e;
            bf16 hv[4], lv[4];
            bsplit(o4.x, hv[0], lv[0]); bsplit(o4.y, hv[1], lv[1]);
            bsplit(o4.z, hv[2], lv[2]); bsplit(o4.w, hv[3], lv[3]);
            *(uint2*)&Ch[o] = *(uint2*)hv;
            *(uint2*)&Cl[o] = *(uint2*)lv;
        }
    }
}

// ---------------- tensor-core flash attention v3 (term-major MMA issue) ----------------
#define LDQ 72
#define LDKV 72
#define LDP 72
#define LDSS 68
#define ATT_KV_STAGE (4*64*LDKV)
#define ATT_SMEM 182272
__global__ __launch_bounds__(256, 1) void attn_tc(
    const bf16* __restrict__ Qh_, const bf16* __restrict__ Ql_,
    const bf16* __restrict__ Kh_, const bf16* __restrict__ Kl_,
    const bf16* __restrict__ Vh_, const bf16* __restrict__ Vl_,
    bf16* __restrict__ Oh_, bf16* __restrict__ Ol_)
{
    extern __shared__ __align__(16) char smraw_[];
    bf16* sQh = (bf16*)smraw_;
    bf16* sQl = sQh + 128 * LDQ;
    bf16* sKV = sQl + 128 * LDQ;
    bf16* sPh = sKV + 2 * ATT_KV_STAGE;
    bf16* sPl = sPh + 128 * LDP;
    float* sS = (float*)(sPl + 128 * LDP);

    int tid = threadIdx.x;
    int warp = tid >> 5;
    int bh = blockIdx.y;
    int q0 = blockIdx.x * 128;
    size_t qoff = ((size_t)bh * SS + q0) * HDD;
    size_t bhoff = (size_t)bh * SS * HDD;

#pragma unroll
    for (int i = 0; i < 4; i++) {
        int idx = tid + i * 256;
        int r = idx >> 3, c8 = (idx & 7) * 8;
        *(uint4*)&sQh[r * LDQ + c8] = *(const uint4*)&Qh_[qoff + (size_t)r * HDD + c8];
        *(uint4*)&sQl[r * LDQ + c8] = *(const uint4*)&Ql_[qoff + (size_t)r * HDD + c8];
    }

    auto kv_issue = [&](int it, int st) {
        size_t koff = bhoff + (size_t)(it * 64) * HDD;
        bf16* kh = sKV + st * ATT_KV_STAGE;
        bf16* kl = kh + 64 * LDKV;
        bf16* vh = kl + 64 * LDKV;
        bf16* vl = vh + 64 * LDKV;
#pragma unroll
        for (int i = 0; i < 2; i++) {
            int idx = tid + i * 256;
            int rr = idx >> 3, c8 = (idx & 7) * 8;
            size_t g = koff + (size_t)rr * HDD + c8;
            __pipeline_memcpy_async(&kh[rr * LDKV + c8], &Kh_[g], 16);
            __pipeline_memcpy_async(&kl[rr * LDKV + c8], &Kl_[g], 16);
            __pipeline_memcpy_async(&vh[rr * LDKV + c8], &Vh_[g], 16);
            __pipeline_memcpy_async(&vl[rr * LDKV + c8], &Vl_[g], 16);
        }
        __pipeline_commit();
    };

    kv_issue(0, 0);
    kv_issue(1, 1);

    wmma::fragment<wmma::accumulator, 16, 16, 16, float> of[4];
#pragma unroll
    for (int j = 0; j < 4; j++) wmma::fill_fragment(of[j], 0.f);

    float l = 0.f;
    int r = tid >> 1, c0 = (tid & 1) * 32;
    const int niter = SS / 64;

    for (int it = 0; it < niter; it++) {
        int st = it & 1;
        __pipeline_wait_prior(1);
        __syncthreads();
        bf16* kh = sKV + st * ATT_KV_STAGE;
        bf16* kl = kh + 64 * LDKV;
        bf16* vh = kl + 64 * LDKV;
        bf16* vl = vh + 64 * LDKV;

        // ---- S = Qh*Kh + Qh*Kl + Ql*Kh (term-major per ks) ----
        {
            wmma::fragment<wmma::accumulator, 16, 16, 16, float> sf[4];
#pragma unroll
            for (int j = 0; j < 4; j++) wmma::fill_fragment(sf[j], 0.f);
#pragma unroll
            for (int ks = 0; ks < 4; ks++) {
                wmma::fragment<wmma::matrix_a, 16, 16, 16, bf16, wmma::row_major> ah, al;
                wmma::fragment<wmma::matrix_b, 16, 16, 16, bf16, wmma::col_major> bhf[4], blf[4];
                wmma::load_matrix_sync(ah, &sQh[(warp * 16) * LDQ + ks * 16], LDQ);
                wmma::load_matrix_sync(al, &sQl[(warp * 16) * LDQ + ks * 16], LDQ);
#pragma unroll
                for (int j = 0; j < 4; j++) {
                    wmma::load_matrix_sync(bhf[j], &kh[(j * 16) * LDKV + ks * 16], LDKV);
                    wmma::load_matrix_sync(blf[j], &kl[(j * 16) * LDKV + ks * 16], LDKV);
                }
#pragma unroll
                for (int j = 0; j < 4; j++) wmma::mma_sync(sf[j], ah, bhf[j], sf[j]);
#pragma unroll
                for (int j = 0; j < 4; j++) wmma::mma_sync(sf[j], ah, blf[j], sf[j]);
#pragma unroll
                for (int j = 0; j < 4; j++) wmma::mma_sync(sf[j], al, bhf[j], sf[j]);
            }
#pragma unroll
            for (int j = 0; j < 4; j++)
                wmma::store_matrix_sync(&sS[(warp * 16) * LDSS + j * 16], sf[j], LDSS, wmma::mem_row_major);
        }
        __syncthreads();

        // ---- max-free softmax ----
        {
            const float* srow = sS + r * LDSS + c0;
            unsigned* ph = (unsigned*)&sPh[r * LDP + c0];
            unsigned* pl = (unsigned*)&sPl[r * LDP + c0];
            float sum = 0.f;
#pragma unroll
            for (int cc = 0; cc < 8; cc++) {
                float4 sv = *(const float4*)&srow[cc * 4];
                float p0 = __expf(sv.x), p1 = __expf(sv.y);
                float p2 = __expf(sv.z), p3 = __expf(sv.w);
                sum += (p0 + p1) + (p2 + p3);
                bf16 h0, l0, h1, l1, h2, l2, h3, l3;
                bsplit(p0, h0, l0); bsplit(p1, h1, l1);
                bsplit(p2, h2, l2); bsplit(p3, h3, l3);
                uint2 uh = { pack2(h0, h1), pack2(h2, h3) };
                uint2 ul = { pack2(l0, l1), pack2(l2, l3) };
                *(uint2*)&ph[cc * 2] = uh;
                *(uint2*)&pl[cc * 2] = ul;
            }
            l += sum;
        }
        __syncthreads();

        // ---- of += Ph*Vh + Pl*Vh + Ph*Vl (term-major per ks) ----
        {
#pragma unroll
            for (int ks = 0; ks < 4; ks++) {
                wmma::fragment<wmma::matrix_a, 16, 16, 16, bf16, wmma::row_major> pah, pal;
                wmma::fragment<wmma::matrix_b, 16, 16, 16, bf16, wmma::row_major> vbh[4], vbl[4];
                wmma::load_matrix_sync(pah, &sPh[(warp * 16) * LDP + ks * 16], LDP);
                wmma::load_matrix_sync(pal, &sPl[(warp * 16) * LDP + ks * 16], LDP);
#pragma unroll
                for (int j = 0; j < 4; j++) {
                    wmma::load_matrix_sync(vbh[j], &vh[(ks * 16) * LDKV + j * 16], LDKV);
                    wmma::load_matrix_sync(vbl[j], &vl[(ks * 16) * LDKV + j * 16], LDKV);
                }
#pragma unroll
                for (int j = 0; j < 4; j++) wmma::mma_sync(of[j], pah, vbh[j], of[j]);
#pragma unroll
                for (int j = 0; j < 4; j++) wmma::mma_sync(of[j], pal, vbh[j], of[j]);
#pragma unroll
                for (int j = 0; j < 4; j++) wmma::mma_sync(of[j], pah, vbl[j], of[j]);
            }
        }
        __syncthreads();

        if (it + 2 < niter) kv_issue(it + 2, st);
        else __pipeline_commit();
    }

    // ---- finalize ----
    l += __shfl_xor_sync(0xffffffffu, l, 1);
#pragma unroll
    for (int j = 0; j < 4; j++)
        wmma::store_matrix_sync(&sS[(warp * 16) * LDSS + j * 16], of[j], LDSS, wmma::mem_row_major);
    __syncthreads();

    int b = bh / HH, hd = bh % HH;
    float inv = 1.0f / l;
    size_t obase = ((size_t)(b * SS + q0 + r)) * DD + hd * HDD + c0;
    const float* orow = sS + r * LDSS + c0;
#pragma unroll
    for (int cc = 0; cc < 8; cc++) {
        float4 ov = *(const float4*)&orow[cc * 4];
        bf16 h0, l0, h1, l1, h2, l2, h3, l3;
        bsplit(ov.x * inv, h0, l0); bsplit(ov.y * inv, h1, l1);
        bsplit(ov.z * inv, h2, l2); bsplit(ov.w * inv, h3, l3);
        uint2 uh = { pack2(h0, h1), pack2(h2, h3) };
        uint2 ul = { pack2(l0, l1), pack2(l2, l3) };
        *(uint2*)&Oh_[obase + cc * 4] = uh;
        *(uint2*)&Ol_[obase + cc * 4] = ul;
    }
}

// ---------------- launch ----------------
extern "C" void kernel_launch(void* const* d_in, const int* in_sizes, int n_in,
                              void* d_out, int out_size) {
    const float* x    = (const float*)d_in[0];
    const float* anw  = (const float*)d_in[1];
    const float* anb  = (const float*)d_in[2];
    const float* Uq   = (const float*)d_in[3];
    const float* Vq   = (const float*)d_in[4];
    const float* bq   = (const float*)d_in[5];
    const float* Uk   = (const float*)d_in[6];
    const float* Vk   = (const float*)d_in[7];
    const float* bk   = (const float*)d_in[8];
    const float* Uv   = (const float*)d_in[9];
    const float* Vv   = (const float*)d_in[10];
    const float* bv   = (const float*)d_in[11];
    const float* Wo_w = (const float*)d_in[12];
    const float* Wo_b = (const float*)d_in[13];
    const float* mnw  = (const float*)d_in[14];
    const float* mnb  = (const float*)d_in[15];
    const float* Ui   = (const float*)d_in[16];
    const float* Vi   = (const float*)d_in[17];
    const float* bi   = (const float*)d_in[18];
    const float* Uo   = (const float*)d_in[19];
    const float* Vo   = (const float*)d_in[20];
    const float* bo   = (const float*)d_in[21];
    const float* cosT = (const float*)d_in[22];
    const float* sinT = (const float*)d_in[23];
    float* out = (float*)d_out;

    bf16 *hh,*hl,*weffh,*weffl,*woth,*wotl,*uih,*uil,*vih,*vil,*uoh,*uol,*voh,*vol;
    bf16 *qh,*ql,*kh,*kl,*vh,*vl,*oh,*ol,*h2h,*h2l,*t1h,*t1l,*gh,*gl,*t2h,*t2l;
    float *x1;
    cudaGetSymbolAddress((void**)&hh, g_hh);   cudaGetSymbolAddress((void**)&hl, g_hl);
    cudaGetSymbolAddress((void**)&weffh, g_weffh); cudaGetSymbolAddress((void**)&weffl, g_weffl);
    cudaGetSymbolAddress((void**)&woth, g_woth);   cudaGetSymbolAddress((void**)&wotl, g_wotl);
    cudaGetSymbolAddress((void**)&uih, g_uih); cudaGetSymbolAddress((void**)&uil, g_uil);
    cudaGetSymbolAddress((void**)&vih, g_vih); cudaGetSymbolAddress((void**)&vil, g_vil);
    cudaGetSymbolAddress((void**)&uoh, g_uoh); cudaGetSymbolAddress((void**)&uol, g_uol);
    cudaGetSymbolAddress((void**)&voh, g_voh); cudaGetSymbolAddress((void**)&vol, g_vol);
    cudaGetSymbolAddress((void**)&qh, g_qh); cudaGetSymbolAddress((void**)&ql, g_ql);
    cudaGetSymbolAddress((void**)&kh, g_kh); cudaGetSymbolAddress((void**)&kl, g_kl);
    cudaGetSymbolAddress((void**)&vh, g_vh); cudaGetSymbolAddress((void**)&vl, g_vl);
    cudaGetSymbolAddress((void**)&oh, g_oh); cudaGetSymbolAddress((void**)&ol, g_ol);
    cudaGetSymbolAddress((void**)&x1, g_x1);
    cudaGetSymbolAddress((void**)&h2h, g_h2h); cudaGetSymbolAddress((void**)&h2l, g_h2l);
    cudaGetSymbolAddress((void**)&t1h, g_t1h); cudaGetSymbolAddress((void**)&t1l, g_t1l);
    cudaGetSymbolAddress((void**)&gh, g_gh); cudaGetSymbolAddress((void**)&gl, g_gl);
    cudaGetSymbolAddress((void**)&t2h, g_t2h); cudaGetSymbolAddress((void**)&t2l, g_t2l);

    cudaFuncSetAttribute(attn_tc, cudaFuncAttributeMaxDynamicSharedMemorySize, ATT_SMEM);
    cudaFuncSetAttribute(gemm_bf3<0>, cudaFuncAttributeMaxDynamicSharedMemorySize, GEMM_SMEM);
    cudaFuncSetAttribute(gemm_bf3<2>, cudaFuncAttributeMaxDynamicSharedMemorySize, GEMM_SMEM);
    cudaFuncSetAttribute(gemm_bf3<3>, cudaFuncAttributeMaxDynamicSharedMemorySize, GEMM_SMEM);
    cudaFuncSetAttribute(gemm_bf3<4>, cudaFuncAttributeMaxDynamicSharedMemorySize, GEMM_SMEM);
    cudaFuncSetAttribute(gemm_bf3<5>, cudaFuncAttributeMaxDynamicSharedMemorySize, GEMM_SMEM);

    // 1. LN1
    ln_split<<<ROWS, 256>>>(x, anw, anb, hh, hl);
    // 2. weights -> hi/lo
    weff_kernel<<<(3 * DD * DD + 255) / 256, 256>>>(Uq, Vq, Uk, Vk, Uv, Vv, weffh, weffl);
    wo_t_split<<<(DD * DD + 255) / 256, 256>>>(Wo_w, woth, wotl);
    split_kernel<<<(DD * RF + 255) / 256, 256>>>(Ui, uih, uil, DD * RF);
    vi_perm_split<<<(RF * 2 * DFF + 255) / 256, 256>>>(Vi, vih, vil);
    split_kernel<<<(DFF * RF + 255) / 256, 256>>>(Uo, uoh, uol, DFF * RF);
    split_kernel<<<(RF * DD + 255) / 256, 256>>>(Vo, voh, vol, RF * DD);
    // 3. Q/K fused rope+scale+split, V scatter+split
    dim3 gQKV(DD / 128, ROWS / 128);
    gemm_bf3<5><<<gQKV, 256, GEMM_SMEM>>>(hh, hl, weffh,           weffl,           bq, nullptr, cosT, sinT, 0.125f, nullptr, qh, ql, ROWS, DD, DD);
    gemm_bf3<5><<<gQKV, 256, GEMM_SMEM>>>(hh, hl, weffh + DD * DD, weffl + DD * DD, bk, nullptr, cosT, sinT, 1.0f,   nullptr, kh, kl, ROWS, DD, DD);
    gemm_bf3<3><<<gQKV, 256, GEMM_SMEM>>>(hh, hl, weffh + 2*DD*DD, weffl + 2*DD*DD, bv, nullptr, nullptr, nullptr, 1.f, nullptr, vh, vl, ROWS, DD, DD);
    // 4. tensor-core attention (max-free flash)
    attn_tc<<<dim3(SS / 128, BB * HH), 256, ATT_SMEM>>>(qh, ql, kh, kl, vh, vl, oh, ol);
    // 5. x1 = x + o @ Wo^T + Wo_b
    gemm_bf3<0><<<dim3(DD / 128, ROWS / 128), 256, GEMM_SMEM>>>(oh, ol, woth, wotl, Wo_b, x, nullptr, nullptr, 1.f, x1, nullptr, nullptr, ROWS, DD, DD);
    // 6. LN2
    ln_split<<<ROWS, 256>>>(x1, mnw, mnb, h2h, h2l);
    // 7. t1 = h2 @ Ui
    gemm_bf3<2><<<dim3(RF / 128, ROWS / 128), 256, GEMM_SMEM>>>(h2h, h2l, uih, uil, nullptr, nullptr, nullptr, nullptr, 1.f, nullptr, t1h, t1l, ROWS, RF, DD);
    // 8. g = GEGLU(t1 @ ViP + biP) fused
    gemm_bf3<4><<<dim3(2 * DFF / 128, ROWS / 128), 256, GEMM_SMEM>>>(t1h, t1l, vih, vil, bi, nullptr, nullptr, nullptr, 1.f, nullptr, gh, gl, ROWS, 2 * DFF, RF);
    // 9. t2 = g @ Uo
    gemm_bf3<2><<<dim3(RF / 128, ROWS / 128), 256, GEMM_SMEM>>>(gh, gl, uoh, uol, nullptr, nullptr, nullptr, nullptr, 1.f, nullptr, t2h, t2l, ROWS, RF, DFF);
    // 10. out = x1 + t2 @ Vo + bo
    gemm_bf3<0><<<dim3(DD / 128, ROWS / 128), 256, GEMM_SMEM>>>(t2h, t2l, voh, vol, bo, x1, nullptr, nullptr, 1.f, out, nullptr, nullptr, ROWS, DD, RF);
}

// round 10
// speedup vs baseline: 1.0727x; 1.0727x over previous
#include <cuda_runtime.h>
#include <cuda_bf16.h>
#include <cuda_pipeline.h>
#include <mma.h>
#include <math.h>
#include <cstdint>

using namespace nvcuda;

// ---------------- problem constants ----------------
#define BB 4
#define SS 2048
#define DD 768
#define HH 12
#define HDD 64
#define RA 32
#define RF 512
#define DFF 3072
#define ROWS (BB*SS)          // 8192

// ---------------- GEMM tile constants ----------------
#define BK 32
#define LDAs 40               // bf16 elems (80B rows, 16B aligned)
#define LDBs 136              // bf16 elems (272B rows)
#define A_TILE (128*LDAs)     // 5120
#define B_TILE (BK*LDBs)      // 4352
#define STAGE (2*A_TILE + 2*B_TILE)   // 18944 bf16
#define GEMM_SMEM (2*STAGE*2)         // 75776 bytes
#define LDC 132               // Csm floats: 128*132*4 = 67584 <= 75776

typedef __nv_bfloat16 bf16;

// ---------------- scratch ----------------
__device__ bf16  g_hh [ROWS*DD];
__device__ bf16  g_hl [ROWS*DD];
__device__ bf16  g_weffh[3*DD*DD];     // [which][k][n]
__device__ bf16  g_weffl[3*DD*DD];
__device__ bf16  g_woth[DD*DD];        // Wo^T [k][n]
__device__ bf16  g_wotl[DD*DD];
__device__ bf16  g_uih[DD*RF],  g_uil[DD*RF];
__device__ bf16  g_vih[RF*2*DFF], g_vil[RF*2*DFF];    // column-interleaved (g1,g2 pairs)
__device__ bf16  g_uoh[DFF*RF], g_uol[DFF*RF];
__device__ bf16  g_voh[RF*DD],  g_vol[RF*DD];
__device__ bf16  g_qh [ROWS*DD], g_ql[ROWS*DD];   // [B,H,S,HD] post-rope, q scaled
__device__ bf16  g_kh [ROWS*DD], g_kl[ROWS*DD];
__device__ bf16  g_vh [ROWS*DD], g_vl[ROWS*DD];
__device__ bf16  g_oh [ROWS*DD], g_ol[ROWS*DD];
__device__ float g_x1 [ROWS*DD];
__device__ bf16  g_h2h[ROWS*DD], g_h2l[ROWS*DD];
__device__ bf16  g_t1h[ROWS*RF], g_t1l[ROWS*RF];
__device__ bf16  g_gh [ROWS*DFF], g_gl[ROWS*DFF];
__device__ bf16  g_t2h[ROWS*RF], g_t2l[ROWS*RF];

__device__ __forceinline__ void bsplit(float a, bf16& h, bf16& l) {
    h = __float2bfloat16(a);
    l = __float2bfloat16(a - __bfloat162float(h));
}
__device__ __forceinline__ unsigned pack2(bf16 a, bf16 b) {
    __nv_bfloat162 t(a, b);
    return *(unsigned*)&t;
}
__device__ __forceinline__ float gelu_t(float x) {
    float t = 0.7978845608028654f * (x + 0.044715f * x * x * x);
    return 0.5f * x * (1.0f + tanhf(t));
}

// ---------------- layernorm -> bf16 hi/lo (warp-shuffle reduction) ----------------
__global__ __launch_bounds__(256) void ln_split(const float* __restrict__ x,
                                                const float* __restrict__ w,
                                                const float* __restrict__ b,
                                                bf16* __restrict__ oh,
                                                bf16* __restrict__ ol) {
    int row = blockIdx.x;
    const float* xr = x + (size_t)row * DD;
    float vals[3];
    float s = 0.f, s2 = 0.f;
    int tid = threadIdx.x;
#pragma unroll
    for (int i = 0; i < 3; i++) {
        float v = xr[tid + i * 256];
        vals[i] = v; s += v; s2 += v * v;
    }
#pragma unroll
    for (int off = 16; off > 0; off >>= 1) {
        s  += __shfl_xor_sync(0xffffffffu, s,  off);
        s2 += __shfl_xor_sync(0xffffffffu, s2, off);
    }
    __shared__ float sh[8], sh2[8];
    int warp = tid >> 5, lane = tid & 31;
    if (lane == 0) { sh[warp] = s; sh2[warp] = s2; }
    __syncthreads();
    float ts = 0.f, ts2 = 0.f;
#pragma unroll
    for (int i = 0; i < 8; i++) { ts += sh[i]; ts2 += sh2[i]; }
    float mean = ts * (1.0f / DD);
    float var  = ts2 * (1.0f / DD) - mean * mean;
    float rstd = rsqrtf(var + 1e-6f);
#pragma unroll
    for (int i = 0; i < 3; i++) {
        int c = tid + i * 256;
        float y = (vals[i] - mean) * rstd * w[c] + b[c];
        bsplit(y, oh[(size_t)row * DD + c], ol[(size_t)row * DD + c]);
    }
}

// ---------------- effective weight -> hi/lo ([k][n]) ----------------
__global__ __launch_bounds__(256) void weff_kernel(const float* __restrict__ Uq, const float* __restrict__ Vq,
                                                   const float* __restrict__ Uk, const float* __restrict__ Vk,
                                                   const float* __restrict__ Uv, const float* __restrict__ Vv,
                                                   bf16* __restrict__ wh, bf16* __restrict__ wl) {
    int idx = blockIdx.x * 256 + threadIdx.x;
    if (idx >= 3 * DD * DD) return;
    int which = idx / (DD * DD);
    int rem = idx % (DD * DD);
    int d = rem / DD, j = rem % DD;
    int hh = j >> 6, e = j & 63;
    const float* U = (which == 0) ? Uq : (which == 1) ? Uk : Uv;
    const float* V = (which == 0) ? Vq : (which == 1) ? Vk : Vv;
    const float* Uhd = U + ((size_t)hh * DD + d) * RA;
    const float* Vh  = V + (size_t)hh * RA * HDD + e;
    float acc = 0.f;
#pragma unroll
    for (int r = 0; r < RA; r++) acc += Uhd[r] * Vh[r * HDD];
    bsplit(acc, wh[idx], wl[idx]);
}

// ---------------- splits ----------------
__global__ __launch_bounds__(256) void split_kernel(const float* __restrict__ in,
                                                    bf16* __restrict__ oh, bf16* __restrict__ ol, int n) {
    int i = blockIdx.x * 256 + threadIdx.x;
    if (i < n) bsplit(in[i], oh[i], ol[i]);
}
__global__ __launch_bounds__(256) void wo_t_split(const float* __restrict__ Wo,
                                                  bf16* __restrict__ oh, bf16* __restrict__ ol) {
    int idx = blockIdx.x * 256 + threadIdx.x;
    if (idx >= DD * DD) return;
    int k = idx / DD, n = idx % DD;
    bsplit(Wo[(size_t)n * DD + k], oh[idx], ol[idx]);
}
// Vi [RF, 2*DFF] -> interleaved columns
__global__ __launch_bounds__(256) void vi_perm_split(const float* __restrict__ Vi,
                                                     bf16* __restrict__ oh, bf16* __restrict__ ol) {
    int idx = blockIdx.x * 256 + threadIdx.x;
    if (idx >= RF * 2 * DFF) return;
    int k = idx / (2 * DFF), n = idx % (2 * DFF);
    int j = n >> 1;
    int srcn = (n & 1) ? (DFF + j) : j;
    bsplit(Vi[(size_t)k * (2 * DFF) + srcn], oh[idx], ol[idx]);
}

// ---------------- shared GEMM mainloop (R8-proven interleaved order) ----------------
struct GemmCore {
    wmma::fragment<wmma::accumulator, 16, 16, 16, float> cf[4][2];
};

__device__ __forceinline__ void gemm_mainloop(
    GemmCore& gc, bf16* smb, int tid, int warp_m, int warp_n,
    const bf16* Agh, const bf16* Agl, const bf16* Bgh, const bf16* Bgl,
    int m0, int n0, int N, int K)
{
    auto issue = [&](int c, int st) {
        int k0 = c * BK;
        bf16* sAh = smb + st * STAGE;
        bf16* sAl = sAh + A_TILE;
        bf16* sBh = sAl + A_TILE;
        bf16* sBl = sBh + B_TILE;
#pragma unroll
        for (int i = 0; i < 2; i++) {
            int t = tid + i * 256;
            int ar = t >> 2;
            int ac = (t & 3) * 8;
            size_t ag = (size_t)(m0 + ar) * K + k0 + ac;
            __pipeline_memcpy_async(&sAh[ar * LDAs + ac], &Agh[ag], 16);
            __pipeline_memcpy_async(&sAl[ar * LDAs + ac], &Agl[ag], 16);
            int br = t >> 4;
            int bc = (t & 15) * 8;
            size_t bg = (size_t)(k0 + br) * N + n0 + bc;
            __pipeline_memcpy_async(&sBh[br * LDBs + bc], &Bgh[bg], 16);
            __pipeline_memcpy_async(&sBl[br * LDBs + bc], &Bgl[bg], 16);
        }
    };

#pragma unroll
    for (int i = 0; i < 4; i++)
#pragma unroll
        for (int j = 0; j < 2; j++) wmma::fill_fragment(gc.cf[i][j], 0.0f);

    int nch = K / BK;
    issue(0, 0); __pipeline_commit();
    if (nch > 1) issue(1, 1);
    __pipeline_commit();

    for (int c = 0; c < nch; c++) {
        __pipeline_wait_prior(1);
        __syncthreads();
        int st = c & 1;
        bf16* sAh = smb + st * STAGE;
        bf16* sAl = sAh + A_TILE;
        bf16* sBh = sAl + A_TILE;
        bf16* sBl = sBh + B_TILE;
#pragma unroll
        for (int ks = 0; ks < 2; ks++) {
            wmma::fragment<wmma::matrix_b, 16, 16, 16, bf16, wmma::row_major> bh[2], bl[2];
#pragma unroll
            for (int j = 0; j < 2; j++) {
                wmma::load_matrix_sync(bh[j], &sBh[(ks * 16) * LDBs + warp_n * 32 + j * 16], LDBs);
                wmma::load_matrix_sync(bl[j], &sBl[(ks * 16) * LDBs + warp_n * 32 + j * 16], LDBs);
            }
#pragma unroll
            for (int i = 0; i < 4; i++) {
                wmma::fragment<wmma::matrix_a, 16, 16, 16, bf16, wmma::row_major> ah, al;
                wmma::load_matrix_sync(ah, &sAh[(warp_m * 64 + i * 16) * LDAs + ks * 16], LDAs);
                wmma::load_matrix_sync(al, &sAl[(warp_m * 64 + i * 16) * LDAs + ks * 16], LDAs);
#pragma unroll
                for (int j = 0; j < 2; j++) {
                    wmma::mma_sync(gc.cf[i][j], ah, bh[j], gc.cf[i][j]);
                    wmma::mma_sync(gc.cf[i][j], ah, bl[j], gc.cf[i][j]);
                    wmma::mma_sync(gc.cf[i][j], al, bh[j], gc.cf[i][j]);
                }
            }
        }
        __syncthreads();
        if (c + 2 < nch) issue(c + 2, st);
        __pipeline_commit();
    }
}

__device__ __forceinline__ void gemm_store_frags(GemmCore& gc, float* Csm, int warp_m, int warp_n) {
#pragma unroll
    for (int i = 0; i < 4; i++)
#pragma unroll
        for (int j = 0; j < 2; j++)
            wmma::store_matrix_sync(&Csm[(warp_m * 64 + i * 16) * LDC + warp_n * 32 + j * 16],
                                    gc.cf[i][j], LDC, wmma::mem_row_major);
}

// ---------------- fused QKV GEMM (z: 0=Q rope*0.125, 1=K rope*1, 2=V plain scatter) ----------------
__global__ __launch_bounds__(256, 2) void gemm_qkv(
    const bf16* __restrict__ Agh, const bf16* __restrict__ Agl,
    const bf16* __restrict__ Wh, const bf16* __restrict__ Wl,
    const float* __restrict__ bq, const float* __restrict__ bk, const float* __restrict__ bv,
    const float* __restrict__ cosT, const float* __restrict__ sinT,
    bf16* __restrict__ Qh, bf16* __restrict__ Ql,
    bf16* __restrict__ Kh, bf16* __restrict__ Kl,
    bf16* __restrict__ Vh, bf16* __restrict__ Vl)
{
    extern __shared__ __align__(16) char smraw[];
    bf16* smb = (bf16*)smraw;
    int tid = threadIdx.x;
    int wid = tid >> 5;
    int warp_m = wid >> 2, warp_n = wid & 3;
    int m0 = blockIdx.y * 128, n0 = blockIdx.x * 128;
    int z = blockIdx.z;

    const bf16* Bgh = Wh + (size_t)z * DD * DD;
    const bf16* Bgl = Wl + (size_t)z * DD * DD;
    const float* bias = (z == 0) ? bq : (z == 1) ? bk : bv;
    bf16* Ch = (z == 0) ? Qh : (z == 1) ? Kh : Vh;
    bf16* Cl = (z == 0) ? Ql : (z == 1) ? Kl : Vl;
    float scale = (z == 0) ? 0.125f : 1.0f;

    GemmCore gc;
    gemm_mainloop(gc, smb, tid, warp_m, warp_n, Agh, Agl, Bgh, Bgl, m0, n0, DD, DD);

    float* Csm = (float*)smraw;
    gemm_store_frags(gc, Csm, warp_m, warp_n);
    __syncthreads();

#pragma unroll
    for (int it = 0; it < 16; it++) {
        int idx = tid + it * 256;
        int r = idx >> 5;
        int c4 = (idx & 31) << 2;
        float4 v = *(const float4*)&Csm[r * LDC + c4];
        int m = m0 + r, n = n0 + c4;
        int e = n & 63;
        int s = m & 2047;
        int b = m >> 11, head = n >> 6;
        size_t o = (((size_t)b * HH + head) * SS + s) * HDD + e;
        if (z == 2) {
            float4 bb = *(const float4*)&bias[n];
            v.x += bb.x; v.y += bb.y; v.z += bb.z; v.w += bb.w;
            bf16 hv[4], lv[4];
            bsplit(v.x, hv[0], lv[0]); bsplit(v.y, hv[1], lv[1]);
            bsplit(v.z, hv[2], lv[2]); bsplit(v.w, hv[3], lv[3]);
            *(uint2*)&Ch[o] = *(uint2*)hv;
            *(uint2*)&Cl[o] = *(uint2*)lv;
        } else {
            float4 p = *(const float4*)&Csm[r * LDC + (c4 ^ 32)];
            float4 bb = *(const float4*)&bias[n];
            v.x += bb.x; v.y += bb.y; v.z += bb.z; v.w += bb.w;
            float4 pb = *(const float4*)&bias[n ^ 32];
            p.x += pb.x; p.y += pb.y; p.z += pb.z; p.w += pb.w;
            float4 cs = *(const float4*)&cosT[s * HDD + e];
            float4 sn = *(const float4*)&sinT[s * HDD + e];
            float4 o4;
            if (e < 32) {
                o4.x = v.x * cs.x - p.x * sn.x; o4.y = v.y * cs.y - p.y * sn.y;
                o4.z = v.z * cs.z - p.z * sn.z; o4.w = v.w * cs.w - p.w * sn.w;
            } else {
                o4.x = v.x * cs.x + p.x * sn.x; o4.y = v.y * cs.y + p.y * sn.y;
                o4.z = v.z * cs.z + p.z * sn.z; o4.w = v.w * cs.w + p.w * sn.w;
            }
            o4.x *= scale; o4.y *= scale; o4.z *= scale; o4.w *= scale;
            bf16 hv[4], lv[4];
            bsplit(o4.x, hv[0], lv[0]); bsplit(o4.y, hv[1], lv[1]);
            bsplit(o4.z, hv[2], lv[2]); bsplit(o4.w, hv[3], lv[3]);
            *(uint2*)&Ch[o] = *(uint2*)hv;
            *(uint2*)&Cl[o] = *(uint2*)lv;
        }
    }
}

// ---------------- generic bf16x3 GEMM (OUTMODE: 0 fp32+bias+res; 2 split; 4 GEGLU) ----------------
template<int OUTMODE>
__global__ __launch_bounds__(256, 2) void gemm_bf3(
    const bf16* __restrict__ Agh, const bf16* __restrict__ Agl,
    const bf16* __restrict__ Bgh, const bf16* __restrict__ Bgl,
    const float* __restrict__ bias, const float* __restrict__ res,
    float* __restrict__ C, bf16* __restrict__ Ch, bf16* __restrict__ Cl,
    int M, int N, int K)
{
    extern __shared__ __align__(16) char smraw[];
    bf16* smb = (bf16*)smraw;
    int tid = threadIdx.x;
    int wid = tid >> 5;
    int warp_m = wid >> 2, warp_n = wid & 3;
    int m0 = blockIdx.y * 128, n0 = blockIdx.x * 128;

    GemmCore gc;
    gemm_mainloop(gc, smb, tid, warp_m, warp_n, Agh, Agl, Bgh, Bgl, m0, n0, N, K);

    float* Csm = (float*)smraw;
    gemm_store_frags(gc, Csm, warp_m, warp_n);
    __syncthreads();

#pragma unroll
    for (int it = 0; it < 16; it++) {
        int idx = tid + it * 256;
        int r = idx >> 5;
        int c4 = (idx & 31) << 2;
        float4 v = *(const float4*)&Csm[r * LDC + c4];
        int m = m0 + r, n = n0 + c4;
        if (OUTMODE != 4) {
            if (bias) {
                float4 bb = *(const float4*)&bias[n];
                v.x += bb.x; v.y += bb.y; v.z += bb.z; v.w += bb.w;
            }
            if (res) {
                float4 rr = *(const float4*)&res[(size_t)m * N + n];
                v.x += rr.x; v.y += rr.y; v.z += rr.z; v.w += rr.w;
            }
        }
        if (OUTMODE == 0) {
            *(float4*)&C[(size_t)m * N + n] = v;
        } else if (OUTMODE == 2) {
            bf16 hv[4], lv[4];
            bsplit(v.x, hv[0], lv[0]); bsplit(v.y, hv[1], lv[1]);
            bsplit(v.z, hv[2], lv[2]); bsplit(v.w, hv[3], lv[3]);
            *(uint2*)&Ch[(size_t)m * N + n] = *(uint2*)hv;
            *(uint2*)&Cl[(size_t)m * N + n] = *(uint2*)lv;
        } else {  // OUTMODE == 4
            int j0 = n >> 1;
            float g1a = v.x + bias[j0];
            float g2a = v.y + bias[DFF + j0];
            float g1b = v.z + bias[j0 + 1];
            float g2b = v.w + bias[DFF + j0 + 1];
            float ga = gelu_t(g1a) * g2a;
            float gb = gelu_t(g1b) * g2b;
            bf16 h0, l0, h1, l1;
            bsplit(ga, h0, l0); bsplit(gb, h1, l1);
            size_t o = (size_t)m * DFF + j0;
            *(unsigned*)&Ch[o] = pack2(h0, h1);
            *(unsigned*)&Cl[o] = pack2(l0, l1);
        }
    }
}

// ---------------- tensor-core flash attention (R8-proven, max-free) ----------------
#define LDQ 72
#define LDKV 72
#define LDP 72
#define LDSS 68
#define ATT_KV_STAGE (4*64*LDKV)
#define ATT_SMEM 182272
__global__ __launch_bounds__(256, 1) void attn_tc(
    const bf16* __restrict__ Qh_, const bf16* __restrict__ Ql_,
    const bf16* __restrict__ Kh_, const bf16* __restrict__ Kl_,
    const bf16* __restrict__ Vh_, const bf16* __restrict__ Vl_,
    bf16* __restrict__ Oh_, bf16* __restrict__ Ol_)
{
    extern __shared__ __align__(16) char smraw_[];
    bf16* sQh = (bf16*)smraw_;
    bf16* sQl = sQh + 128 * LDQ;
    bf16* sKV = sQl + 128 * LDQ;
    bf16* sPh = sKV + 2 * ATT_KV_STAGE;
    bf16* sPl = sPh + 128 * LDP;
    float* sS = (float*)(sPl + 128 * LDP);

    int tid = threadIdx.x;
    int warp = tid >> 5;
    int bh = blockIdx.y;
    int q0 = blockIdx.x * 128;
    size_t qoff = ((size_t)bh * SS + q0) * HDD;
    size_t bhoff = (size_t)bh * SS * HDD;

#pragma unroll
    for (int i = 0; i < 4; i++) {
        int idx = tid + i * 256;
        int r = idx >> 3, c8 = (idx & 7) * 8;
        *(uint4*)&sQh[r * LDQ + c8] = *(const uint4*)&Qh_[qoff + (size_t)r * HDD + c8];
        *(uint4*)&sQl[r * LDQ + c8] = *(const uint4*)&Ql_[qoff + (size_t)r * HDD + c8];
    }

    auto kv_issue = [&](int it, int st) {
        size_t koff = bhoff + (size_t)(it * 64) * HDD;
        bf16* kh = sKV + st * ATT_KV_STAGE;
        bf16* kl = kh + 64 * LDKV;
        bf16* vh = kl + 64 * LDKV;
        bf16* vl = vh + 64 * LDKV;
#pragma unroll
        for (int i = 0; i < 2; i++) {
            int idx = tid + i * 256;
            int rr = idx >> 3, c8 = (idx & 7) * 8;
            size_t g = koff + (size_t)rr * HDD + c8;
            __pipeline_memcpy_async(&kh[rr * LDKV + c8], &Kh_[g], 16);
            __pipeline_memcpy_async(&kl[rr * LDKV + c8], &Kl_[g], 16);
            __pipeline_memcpy_async(&vh[rr * LDKV + c8], &Vh_[g], 16);
            __pipeline_memcpy_async(&vl[rr * LDKV + c8], &Vl_[g], 16);
        }
        __pipeline_commit();
    };

    kv_issue(0, 0);
    kv_issue(1, 1);

    wmma::fragment<wmma::accumulator, 16, 16, 16, float> of[4];
#pragma unroll
    for (int j = 0; j < 4; j++) wmma::fill_fragment(of[j], 0.f);

    float l = 0.f;
    int r = tid >> 1, c0 = (tid & 1) * 32;
    const int niter = SS / 64;

    for (int it = 0; it < niter; it++) {
        int st = it & 1;
        __pipeline_wait_prior(1);
        __syncthreads();
        bf16* kh = sKV + st * ATT_KV_STAGE;
        bf16* kl = kh + 64 * LDKV;
        bf16* vh = kl + 64 * LDKV;
        bf16* vl = vh + 64 * LDKV;

        {
            wmma::fragment<wmma::accumulator, 16, 16, 16, float> sf[4];
#pragma unroll
            for (int j = 0; j < 4; j++) wmma::fill_fragment(sf[j], 0.f);
#pragma unroll
            for (int ks = 0; ks < 4; ks++) {
                wmma::fragment<wmma::matrix_a, 16, 16, 16, bf16, wmma::row_major> ah, al;
                wmma::load_matrix_sync(ah, &sQh[(warp * 16) * LDQ + ks * 16], LDQ);
                wmma::load_matrix_sync(al, &sQl[(warp * 16) * LDQ + ks * 16], LDQ);
#pragma unroll
                for (int j = 0; j < 4; j++) {
                    wmma::fragment<wmma::matrix_b, 16, 16, 16, bf16, wmma::col_major> bhf, blf;
                    wmma::load_matrix_sync(bhf, &kh[(j * 16) * LDKV + ks * 16], LDKV);
                    wmma::load_matrix_sync(blf, &kl[(j * 16) * LDKV + ks * 16], LDKV);
                    wmma::mma_sync(sf[j], ah, bhf, sf[j]);
                    wmma::mma_sync(sf[j], ah, blf, sf[j]);
                    wmma::mma_sync(sf[j], al, bhf, sf[j]);
                }
            }
#pragma unroll
            for (int j = 0; j < 4; j++)
                wmma::store_matrix_sync(&sS[(warp * 16) * LDSS + j * 16], sf[j], LDSS, wmma::mem_row_major);
        }
        __syncthreads();

        {
            const float* srow = sS + r * LDSS + c0;
            unsigned* ph = (unsigned*)&sPh[r * LDP + c0];
            unsigned* pl = (unsigned*)&sPl[r * LDP + c0];
            float sum = 0.f;
#pragma unroll
            for (int cc = 0; cc < 8; cc++) {
                float4 sv = *(const float4*)&srow[cc * 4];
                float p0 = __expf(sv.x), p1 = __expf(sv.y);
                float p2 = __expf(sv.z), p3 = __expf(sv.w);
                sum += (p0 + p1) + (p2 + p3);
                bf16 h0, l0, h1, l1, h2, l2, h3, l3;
                bsplit(p0, h0, l0); bsplit(p1, h1, l1);
                bsplit(p2, h2, l2); bsplit(p3, h3, l3);
                uint2 uh = { pack2(h0, h1), pack2(h2, h3) };
                uint2 ul = { pack2(l0, l1), pack2(l2, l3) };
                *(uint2*)&ph[cc * 2] = uh;
                *(uint2*)&pl[cc * 2] = ul;
            }
            l += sum;
        }
        __syncthreads();

        {
            wmma::fragment<wmma::matrix_a, 16, 16, 16, bf16, wmma::row_major> pah[4], pal[4];
#pragma unroll
            for (int ks = 0; ks < 4; ks++) {
                wmma::load_matrix_sync(pah[ks], &sPh[(warp * 16) * LDP + ks * 16], LDP);
                wmma::load_matrix_sync(pal[ks], &sPl[(warp * 16) * LDP + ks * 16], LDP);
            }
#pragma unroll
            for (int j = 0; j < 4; j++) {
#pragma unroll
                for (int ks = 0; ks < 4; ks++) {
                    wmma::fragment<wmma::matrix_b, 16, 16, 16, bf16, wmma::row_major> vbh, vbl;
                    wmma::load_matrix_sync(vbh, &vh[(ks * 16) * LDKV + j * 16], LDKV);
                    wmma::load_matrix_sync(vbl, &vl[(ks * 16) * LDKV + j * 16], LDKV);
                    wmma::mma_sync(of[j], pah[ks], vbh, of[j]);
                    wmma::mma_sync(of[j], pal[ks], vbh, of[j]);
                    wmma::mma_sync(of[j], pah[ks], vbl, of[j]);
                }
            }
        }
        __syncthreads();

        if (it + 2 < niter) kv_issue(it + 2, st);
        else __pipeline_commit();
    }

    l += __shfl_xor_sync(0xffffffffu, l, 1);
#pragma unroll
    for (int j = 0; j < 4; j++)
        wmma::store_matrix_sync(&sS[(warp * 16) * LDSS + j * 16], of[j], LDSS, wmma::mem_row_major);
    __syncthreads();

    int b = bh / HH, hd = bh % HH;
    float inv = 1.0f / l;
    size_t obase = ((size_t)(b * SS + q0 + r)) * DD + hd * HDD + c0;
    const float* orow = sS + r * LDSS + c0;
#pragma unroll
    for (int cc = 0; cc < 8; cc++) {
        float4 ov = *(const float4*)&orow[cc * 4];
        bf16 h0, l0, h1, l1, h2, l2, h3, l3;
        bsplit(ov.x * inv, h0, l0); bsplit(ov.y * inv, h1, l1);
        bsplit(ov.z * inv, h2, l2); bsplit(ov.w * inv, h3, l3);
        uint2 uh = { pack2(h0, h1), pack2(h2, h3) };
        uint2 ul = { pack2(l0, l1), pack2(l2, l3) };
        *(uint2*)&Oh_[obase + cc * 4] = uh;
        *(uint2*)&Ol_[obase + cc * 4] = ul;
    }
}

// ---------------- launch ----------------
extern "C" void kernel_launch(void* const* d_in, const int* in_sizes, int n_in,
                              void* d_out, int out_size) {
    const float* x    = (const float*)d_in[0];
    const float* anw  = (const float*)d_in[1];
    const float* anb  = (const float*)d_in[2];
    const float* Uq   = (const float*)d_in[3];
    const float* Vq   = (const float*)d_in[4];
    const float* bq   = (const float*)d_in[5];
    const float* Uk   = (const float*)d_in[6];
    const float* Vk   = (const float*)d_in[7];
    const float* bk   = (const float*)d_in[8];
    const float* Uv   = (const float*)d_in[9];
    const float* Vv   = (const float*)d_in[10];
    const float* bv   = (const float*)d_in[11];
    const float* Wo_w = (const float*)d_in[12];
    const float* Wo_b = (const float*)d_in[13];
    const float* mnw  = (const float*)d_in[14];
    const float* mnb  = (const float*)d_in[15];
    const float* Ui   = (const float*)d_in[16];
    const float* Vi   = (const float*)d_in[17];
    const float* bi   = (const float*)d_in[18];
    const float* Uo   = (const float*)d_in[19];
    const float* Vo   = (const float*)d_in[20];
    const float* bo   = (const float*)d_in[21];
    const float* cosT = (const float*)d_in[22];
    const float* sinT = (const float*)d_in[23];
    float* out = (float*)d_out;

    bf16 *hh,*hl,*weffh,*weffl,*woth,*wotl,*uih,*uil,*vih,*vil,*uoh,*uol,*voh,*vol;
    bf16 *qh,*ql,*kh,*kl,*vh,*vl,*oh,*ol,*h2h,*h2l,*t1h,*t1l,*gh,*gl,*t2h,*t2l;
    float *x1;
    cudaGetSymbolAddress((void**)&hh, g_hh);   cudaGetSymbolAddress((void**)&hl, g_hl);
    cudaGetSymbolAddress((void**)&weffh, g_weffh); cudaGetSymbolAddress((void**)&weffl, g_weffl);
    cudaGetSymbolAddress((void**)&woth, g_woth);   cudaGetSymbolAddress((void**)&wotl, g_wotl);
    cudaGetSymbolAddress((void**)&uih, g_uih); cudaGetSymbolAddress((void**)&uil, g_uil);
    cudaGetSymbolAddress((void**)&vih, g_vih); cudaGetSymbolAddress((void**)&vil, g_vil);
    cudaGetSymbolAddress((void**)&uoh, g_uoh); cudaGetSymbolAddress((void**)&uol, g_uol);
    cudaGetSymbolAddress((void**)&voh, g_voh); cudaGetSymbolAddress((void**)&vol, g_vol);
    cudaGetSymbolAddress((void**)&qh, g_qh); cudaGetSymbolAddress((void**)&ql, g_ql);
    cudaGetSymbolAddress((void**)&kh, g_kh); cudaGetSymbolAddress((void**)&kl, g_kl);
    cudaGetSymbolAddress((void**)&vh, g_vh); cudaGetSymbolAddress((void**)&vl, g_vl);
    cudaGetSymbolAddress((void**)&oh, g_oh); cudaGetSymbolAddress((void**)&ol, g_ol);
    cudaGetSymbolAddress((void**)&x1, g_x1);
    cudaGetSymbolAddress((void**)&h2h, g_h2h); cudaGetSymbolAddress((void**)&h2l, g_h2l);
    cudaGetSymbolAddress((void**)&t1h, g_t1h); cudaGetSymbolAddress((void**)&t1l, g_t1l);
    cudaGetSymbolAddress((void**)&gh, g_gh); cudaGetSymbolAddress((void**)&gl, g_gl);
    cudaGetSymbolAddress((void**)&t2h, g_t2h); cudaGetSymbolAddress((void**)&t2l, g_t2l);

    cudaFuncSetAttribute(attn_tc, cudaFuncAttributeMaxDynamicSharedMemorySize, ATT_SMEM);
    cudaFuncSetAttribute(gemm_qkv,   cudaFuncAttributeMaxDynamicSharedMemorySize, GEMM_SMEM);
    cudaFuncSetAttribute(gemm_bf3<0>, cudaFuncAttributeMaxDynamicSharedMemorySize, GEMM_SMEM);
    cudaFuncSetAttribute(gemm_bf3<2>, cudaFuncAttributeMaxDynamicSharedMemorySize, GEMM_SMEM);
    cudaFuncSetAttribute(gemm_bf3<4>, cudaFuncAttributeMaxDynamicSharedMemorySize, GEMM_SMEM);

    // 1. LN1
    ln_split<<<ROWS, 256>>>(x, anw, anb, hh, hl);
    // 2. weights -> hi/lo
    weff_kernel<<<(3 * DD * DD + 255) / 256, 256>>>(Uq, Vq, Uk, Vk, Uv, Vv, weffh, weffl);
    wo_t_split<<<(DD * DD + 255) / 256, 256>>>(Wo_w, woth, wotl);
    split_kernel<<<(DD * RF + 255) / 256, 256>>>(Ui, uih, uil, DD * RF);
    vi_perm_split<<<(RF * 2 * DFF + 255) / 256, 256>>>(Vi, vih, vil);
    split_kernel<<<(DFF * RF + 255) / 256, 256>>>(Uo, uoh, uol, DFF * RF);
    split_kernel<<<(RF * DD + 255) / 256, 256>>>(Vo, voh, vol, RF * DD);
    // 3. fused Q/K/V projections (one launch, 1152 CTAs)
    gemm_qkv<<<dim3(DD / 128, ROWS / 128, 3), 256, GEMM_SMEM>>>(
        hh, hl, weffh, weffl, bq, bk, bv, cosT, sinT, qh, ql, kh, kl, vh, vl);
    // 4. tensor-core attention (max-free flash)
    attn_tc<<<dim3(SS / 128, BB * HH), 256, ATT_SMEM>>>(qh, ql, kh, kl, vh, vl, oh, ol);
    // 5. x1 = x + o @ Wo^T + Wo_b
    gemm_bf3<0><<<dim3(DD / 128, ROWS / 128), 256, GEMM_SMEM>>>(oh, ol, woth, wotl, Wo_b, x, x1, nullptr, nullptr, ROWS, DD, DD);
    // 6. LN2
    ln_split<<<ROWS, 256>>>(x1, mnw, mnb, h2h, h2l);
    // 7. t1 = h2 @ Ui
    gemm_bf3<2><<<dim3(RF / 128, ROWS / 128), 256, GEMM_SMEM>>>(h2h, h2l, uih, uil, nullptr, nullptr, nullptr, t1h, t1l, ROWS, RF, DD);
    // 8. g = GEGLU(t1 @ ViP + biP) fused
    gemm_bf3<4><<<dim3(2 * DFF / 128, ROWS / 128), 256, GEMM_SMEM>>>(t1h, t1l, vih, vil, bi, nullptr, nullptr, gh, gl, ROWS, 2 * DFF, RF);
    // 9. t2 = g @ Uo
    gemm_bf3<2><<<dim3(RF / 128, ROWS / 128), 256, GEMM_SMEM>>>(gh, gl, uoh, uol, nullptr, nullptr, nullptr, t2h, t2l, ROWS, RF, DFF);
    // 10. out = x1 + t2 @ Vo + bo
    gemm_bf3<0><<<dim3(DD / 128, ROWS / 128), 256, GEMM_SMEM>>>(t2h, t2l, voh, vol, bo, x1, out, nullptr, nullptr, ROWS, DD, RF);
}

// round 12
// speedup vs baseline: 1.0791x; 1.0060x over previous
#include <cuda_runtime.h>
#include <cuda_bf16.h>
#include <cuda_pipeline.h>
#include <mma.h>
#include <math.h>
#include <cstdint>

using namespace nvcuda;

// ---------------- problem constants ----------------
#define BB 4
#define SS 2048
#define DD 768
#define HH 12
#define HDD 64
#define RA 32
#define RF 512
#define DFF 3072
#define ROWS (BB*SS)          // 8192

// ---------------- GEMM tile constants ----------------
#define BK 32
#define LDAs 40               // bf16 elems (80B rows, 16B aligned)
#define LDBs 136              // bf16 elems (272B rows)
#define A_TILE (128*LDAs)     // 5120
#define B_TILE (BK*LDBs)      // 4352
#define STAGE (2*A_TILE + 2*B_TILE)   // 18944 bf16
#define GEMM_SMEM (2*STAGE*2)         // 75776 bytes
#define LDC 132               // Csm floats: 128*132*4 = 67584 <= 75776

typedef __nv_bfloat16 bf16;

// ---------------- scratch ----------------
__device__ bf16  g_hh [ROWS*DD];
__device__ bf16  g_hl [ROWS*DD];
__device__ bf16  g_weffh[3*DD*DD];     // [which][k][n]
__device__ bf16  g_weffl[3*DD*DD];
__device__ bf16  g_woth[DD*DD];        // Wo^T [k][n]
__device__ bf16  g_wotl[DD*DD];
__device__ bf16  g_uih[DD*RF],  g_uil[DD*RF];
__device__ bf16  g_vih[RF*2*DFF], g_vil[RF*2*DFF];    // column-interleaved (g1,g2 pairs)
__device__ bf16  g_uoh[DFF*RF], g_uol[DFF*RF];
__device__ bf16  g_voh[RF*DD],  g_vol[RF*DD];
__device__ bf16  g_qh [ROWS*DD], g_ql[ROWS*DD];   // [B,H,S,HD] post-rope, q scaled
__device__ bf16  g_kh [ROWS*DD], g_kl[ROWS*DD];
__device__ bf16  g_vh [ROWS*DD], g_vl[ROWS*DD];
__device__ bf16  g_oh [ROWS*DD], g_ol[ROWS*DD];
__device__ float g_x1 [ROWS*DD];
__device__ bf16  g_h2h[ROWS*DD], g_h2l[ROWS*DD];
__device__ bf16  g_t1h[ROWS*RF], g_t1l[ROWS*RF];
__device__ bf16  g_gh [ROWS*DFF], g_gl[ROWS*DFF];
__device__ bf16  g_t2h[ROWS*RF], g_t2l[ROWS*RF];

__device__ __forceinline__ void bsplit(float a, bf16& h, bf16& l) {
    h = __float2bfloat16(a);
    l = __float2bfloat16(a - __bfloat162float(h));
}
__device__ __forceinline__ unsigned pack2(bf16 a, bf16 b) {
    __nv_bfloat162 t(a, b);
    return *(unsigned*)&t;
}
__device__ __forceinline__ float gelu_t(float x) {
    float t = 0.7978845608028654f * (x + 0.044715f * x * x * x);
    return 0.5f * x * (1.0f + tanhf(t));
}

// ---------------- layernorm -> bf16 hi/lo (warp-shuffle reduction) ----------------
__global__ __launch_bounds__(256) void ln_split(const float* __restrict__ x,
                                                const float* __restrict__ w,
                                                const float* __restrict__ b,
                                                bf16* __restrict__ oh,
                                                bf16* __restrict__ ol) {
    int row = blockIdx.x;
    const float* xr = x + (size_t)row * DD;
    float vals[3];
    float s = 0.f, s2 = 0.f;
    int tid = threadIdx.x;
#pragma unroll
    for (int i = 0; i < 3; i++) {
        float v = xr[tid + i * 256];
        vals[i] = v; s += v; s2 += v * v;
    }
#pragma unroll
    for (int off = 16; off > 0; off >>= 1) {
        s  += __shfl_xor_sync(0xffffffffu, s,  off);
        s2 += __shfl_xor_sync(0xffffffffu, s2, off);
    }
    __shared__ float sh[8], sh2[8];
    int warp = tid >> 5, lane = tid & 31;
    if (lane == 0) { sh[warp] = s; sh2[warp] = s2; }
    __syncthreads();
    float ts = 0.f, ts2 = 0.f;
#pragma unroll
    for (int i = 0; i < 8; i++) { ts += sh[i]; ts2 += sh2[i]; }
    float mean = ts * (1.0f / DD);
    float var  = ts2 * (1.0f / DD) - mean * mean;
    float rstd = rsqrtf(var + 1e-6f);
#pragma unroll
    for (int i = 0; i < 3; i++) {
        int c = tid + i * 256;
        float y = (vals[i] - mean) * rstd * w[c] + b[c];
        bsplit(y, oh[(size_t)row * DD + c], ol[(size_t)row * DD + c]);
    }
}

// ---------------- effective weight -> hi/lo ([k][n]) ----------------
__global__ __launch_bounds__(256) void weff_kernel(const float* __restrict__ Uq, const float* __restrict__ Vq,
                                                   const float* __restrict__ Uk, const float* __restrict__ Vk,
                                                   const float* __restrict__ Uv, const float* __restrict__ Vv,
                                                   bf16* __restrict__ wh, bf16* __restrict__ wl) {
    int idx = blockIdx.x * 256 + threadIdx.x;
    if (idx >= 3 * DD * DD) return;
    int which = idx / (DD * DD);
    int rem = idx % (DD * DD);
    int d = rem / DD, j = rem % DD;
    int hh = j >> 6, e = j & 63;
    const float* U = (which == 0) ? Uq : (which == 1) ? Uk : Uv;
    const float* V = (which == 0) ? Vq : (which == 1) ? Vk : Vv;
    const float* Uhd = U + ((size_t)hh * DD + d) * RA;
    const float* Vh  = V + (size_t)hh * RA * HDD + e;
    float acc = 0.f;
#pragma unroll
    for (int r = 0; r < RA; r++) acc += Uhd[r] * Vh[r * HDD];
    bsplit(acc, wh[idx], wl[idx]);
}

// ---------------- all weight splits in ONE kernel (range dispatch) ----------------
#define N_WOT (DD*DD)
#define N_UI  (DD*RF)
#define N_VI  (RF*2*DFF)
#define N_UO  (DFF*RF)
#define N_VO  (RF*DD)
#define N_ALL (N_WOT+N_UI+N_VI+N_UO+N_VO)
__global__ __launch_bounds__(256) void all_splits(
    const float* __restrict__ Wo, const float* __restrict__ Ui, const float* __restrict__ Vi,
    const float* __restrict__ Uo, const float* __restrict__ Vo,
    bf16* __restrict__ woth, bf16* __restrict__ wotl,
    bf16* __restrict__ uih,  bf16* __restrict__ uil,
    bf16* __restrict__ vih,  bf16* __restrict__ vil,
    bf16* __restrict__ uoh,  bf16* __restrict__ uol,
    bf16* __restrict__ voh,  bf16* __restrict__ vol)
{
    int idx = blockIdx.x * 256 + threadIdx.x;
    if (idx >= N_ALL) return;
    if (idx < N_WOT) {
        int k = idx / DD, n = idx % DD;                 // Wo^T
        bsplit(Wo[(size_t)n * DD + k], woth[idx], wotl[idx]);
        return;
    }
    idx -= N_WOT;
    if (idx < N_UI) { bsplit(Ui[idx], uih[idx], uil[idx]); return; }
    idx -= N_UI;
    if (idx < N_VI) {                                    // Vi perm-interleave
        int k = idx / (2 * DFF), n = idx % (2 * DFF);
        int j = n >> 1;
        int srcn = (n & 1) ? (DFF + j) : j;
        bsplit(Vi[(size_t)k * (2 * DFF) + srcn], vih[idx], vil[idx]);
        return;
    }
    idx -= N_VI;
    if (idx < N_UO) { bsplit(Uo[idx], uoh[idx], uol[idx]); return; }
    idx -= N_UO;
    bsplit(Vo[idx], voh[idx], vol[idx]);
}

// ---------------- shared GEMM mainloop (R8-proven interleaved order) ----------------
struct GemmCore {
    wmma::fragment<wmma::accumulator, 16, 16, 16, float> cf[4][2];
};

__device__ __forceinline__ void gemm_mainloop(
    GemmCore& gc, bf16* smb, int tid, int warp_m, int warp_n,
    const bf16* Agh, const bf16* Agl, const bf16* Bgh, const bf16* Bgl,
    int m0, int n0, int N, int K)
{
    auto issue = [&](int c, int st) {
        int k0 = c * BK;
        bf16* sAh = smb + st * STAGE;
        bf16* sAl = sAh + A_TILE;
        bf16* sBh = sAl + A_TILE;
        bf16* sBl = sBh + B_TILE;
#pragma unroll
        for (int i = 0; i < 2; i++) {
            int t = tid + i * 256;
            int ar = t >> 2;
            int ac = (t & 3) * 8;
            size_t ag = (size_t)(m0 + ar) * K + k0 + ac;
            __pipeline_memcpy_async(&sAh[ar * LDAs + ac], &Agh[ag], 16);
            __pipeline_memcpy_async(&sAl[ar * LDAs + ac], &Agl[ag], 16);
            int br = t >> 4;
            int bc = (t & 15) * 8;
            size_t bg = (size_t)(k0 + br) * N + n0 + bc;
            __pipeline_memcpy_async(&sBh[br * LDBs + bc], &Bgh[bg], 16);
            __pipeline_memcpy_async(&sBl[br * LDBs + bc], &Bgl[bg], 16);
        }
    };

#pragma unroll
    for (int i = 0; i < 4; i++)
#pragma unroll
        for (int j = 0; j < 2; j++) wmma::fill_fragment(gc.cf[i][j], 0.0f);

    int nch = K / BK;
    issue(0, 0); __pipeline_commit();
    if (nch > 1) issue(1, 1);
    __pipeline_commit();

    for (int c = 0; c < nch; c++) {
        __pipeline_wait_prior(1);
        __syncthreads();
        int st = c & 1;
        bf16* sAh = smb + st * STAGE;
        bf16* sAl = sAh + A_TILE;
        bf16* sBh = sAl + A_TILE;
        bf16* sBl = sBh + B_TILE;
#pragma unroll
        for (int ks = 0; ks < 2; ks++) {
            wmma::fragment<wmma::matrix_b, 16, 16, 16, bf16, wmma::row_major> bh[2], bl[2];
#pragma unroll
            for (int j = 0; j < 2; j++) {
                wmma::load_matrix_sync(bh[j], &sBh[(ks * 16) * LDBs + warp_n * 32 + j * 16], LDBs);
                wmma::load_matrix_sync(bl[j], &sBl[(ks * 16) * LDBs + warp_n * 32 + j * 16], LDBs);
            }
#pragma unroll
            for (int i = 0; i < 4; i++) {
                wmma::fragment<wmma::matrix_a, 16, 16, 16, bf16, wmma::row_major> ah, al;
                wmma::load_matrix_sync(ah, &sAh[(warp_m * 64 + i * 16) * LDAs + ks * 16], LDAs);
                wmma::load_matrix_sync(al, &sAl[(warp_m * 64 + i * 16) * LDAs + ks * 16], LDAs);
#pragma unroll
                for (int j = 0; j < 2; j++) {
                    wmma::mma_sync(gc.cf[i][j], ah, bh[j], gc.cf[i][j]);
                    wmma::mma_sync(gc.cf[i][j], ah, bl[j], gc.cf[i][j]);
                    wmma::mma_sync(gc.cf[i][j], al, bh[j], gc.cf[i][j]);
                }
            }
        }
        __syncthreads();
        if (c + 2 < nch) issue(c + 2, st);
        __pipeline_commit();
    }
}

__device__ __forceinline__ void gemm_store_frags(GemmCore& gc, float* Csm, int warp_m, int warp_n) {
#pragma unroll
    for (int i = 0; i < 4; i++)
#pragma unroll
        for (int j = 0; j < 2; j++)
            wmma::store_matrix_sync(&Csm[(warp_m * 64 + i * 16) * LDC + warp_n * 32 + j * 16],
                                    gc.cf[i][j], LDC, wmma::mem_row_major);
}

// ---------------- fused QKV GEMM (z: 0=Q rope*0.125, 1=K rope*1, 2=V split scatter) ----------------
__global__ __launch_bounds__(256, 2) void gemm_qkv(
    const bf16* __restrict__ Agh, const bf16* __restrict__ Agl,
    const bf16* __restrict__ Wh, const bf16* __restrict__ Wl,
    const float* __restrict__ bq, const float* __restrict__ bk, const float* __restrict__ bv,
    const float* __restrict__ cosT, const float* __restrict__ sinT,
    bf16* __restrict__ Qh, bf16* __restrict__ Ql,
    bf16* __restrict__ Kh, bf16* __restrict__ Kl,
    bf16* __restrict__ Vh, bf16* __restrict__ Vl)
{
    extern __shared__ __align__(16) char smraw[];
    bf16* smb = (bf16*)smraw;
    int tid = threadIdx.x;
    int wid = tid >> 5;
    int warp_m = wid >> 2, warp_n = wid & 3;
    int m0 = blockIdx.y * 128, n0 = blockIdx.x * 128;
    int z = blockIdx.z;

    const bf16* Bgh = Wh + (size_t)z * DD * DD;
    const bf16* Bgl = Wl + (size_t)z * DD * DD;
    const float* bias = (z == 0) ? bq : (z == 1) ? bk : bv;
    float scale = (z == 0) ? 0.125f : 1.0f;

    GemmCore gc;
    gemm_mainloop(gc, smb, tid, warp_m, warp_n, Agh, Agl, Bgh, Bgl, m0, n0, DD, DD);

    float* Csm = (float*)smraw;
    gemm_store_frags(gc, Csm, warp_m, warp_n);
    __syncthreads();

#pragma unroll
    for (int it = 0; it < 16; it++) {
        int idx = tid + it * 256;
        int r = idx >> 5;
        int c4 = (idx & 31) << 2;
        float4 v = *(const float4*)&Csm[r * LDC + c4];
        int m = m0 + r, n = n0 + c4;
        int e = n & 63;
        int s = m & 2047;
        int b = m >> 11, head = n >> 6;
        size_t o = (((size_t)b * HH + head) * SS + s) * HDD + e;
        if (z == 2) {
            float4 bb = *(const float4*)&bias[n];
            v.x += bb.x; v.y += bb.y; v.z += bb.z; v.w += bb.w;
            bf16 hv[4], lv[4];
            bsplit(v.x, hv[0], lv[0]); bsplit(v.y, hv[1], lv[1]);
            bsplit(v.z, hv[2], lv[2]); bsplit(v.w, hv[3], lv[3]);
            *(uint2*)&Vh[o] = *(uint2*)hv;
            *(uint2*)&Vl[o] = *(uint2*)lv;
        } else {
            float4 p = *(const float4*)&Csm[r * LDC + (c4 ^ 32)];
            float4 bb = *(const float4*)&bias[n];
            v.x += bb.x; v.y += bb.y; v.z += bb.z; v.w += bb.w;
            float4 pb = *(const float4*)&bias[n ^ 32];
            p.x += pb.x; p.y += pb.y; p.z += pb.z; p.w += pb.w;
            float4 cs = *(const float4*)&cosT[s * HDD + e];
            float4 sn = *(const float4*)&sinT[s * HDD + e];
            float4 o4;
            if (e < 32) {
                o4.x = v.x * cs.x - p.x * sn.x; o4.y = v.y * cs.y - p.y * sn.y;
                o4.z = v.z * cs.z - p.z * sn.z; o4.w = v.w * cs.w - p.w * sn.w;
            } else {
                o4.x = v.x * cs.x + p.x * sn.x; o4.y = v.y * cs.y + p.y * sn.y;
                o4.z = v.z * cs.z + p.z * sn.z; o4.w = v.w * cs.w + p.w * sn.w;
            }
            o4.x *= scale; o4.y *= scale; o4.z *= scale; o4.w *= scale;
            bf16* Ch = (z == 0) ? Qh : Kh;
            bf16* Cl = (z == 0) ? Ql : Kl;
            bf16 hv[4], lv[4];
            bsplit(o4.x, hv[0], lv[0]); bsplit(o4.y, hv[1], lv[1]);
            bsplit(o4.z, hv[2], lv[2]); bsplit(o4.w, hv[3], lv[3]);
            *(uint2*)&Ch[o] = *(uint2*)hv;
            *(uint2*)&Cl[o] = *(uint2*)lv;
        }
    }
}

// ---------------- generic bf16x3 GEMM (OUTMODE: 0 fp32+bias+res; 2 split; 4 GEGLU) ----------------
template<int OUTMODE>
__global__ __launch_bounds__(256, 2) void gemm_bf3(
    const bf16* __restrict__ Agh, const bf16* __restrict__ Agl,
    const bf16* __restrict__ Bgh, const bf16* __restrict__ Bgl,
    const float* __restrict__ bias, const float* __restrict__ res,
    float* __restrict__ C, bf16* __restrict__ Ch, bf16* __restrict__ Cl,
    int M, int N, int K)
{
    extern __shared__ __align__(16) char smraw[];
    bf16* smb = (bf16*)smraw;
    int tid = threadIdx.x;
    int wid = tid >> 5;
    int warp_m = wid >> 2, warp_n = wid & 3;
    int m0 = blockIdx.y * 128, n0 = blockIdx.x * 128;

    GemmCore gc;
    gemm_mainloop(gc, smb, tid, warp_m, warp_n, Agh, Agl, Bgh, Bgl, m0, n0, N, K);

    float* Csm = (float*)smraw;
    gemm_store_frags(gc, Csm, warp_m, warp_n);
    __syncthreads();

#pragma unroll
    for (int it = 0; it < 16; it++) {
        int idx = tid + it * 256;
        int r = idx >> 5;
        int c4 = (idx & 31) << 2;
        float4 v = *(const float4*)&Csm[r * LDC + c4];
        int m = m0 + r, n = n0 + c4;
        if (OUTMODE != 4) {
            if (bias) {
                float4 bb = *(const float4*)&bias[n];
                v.x += bb.x; v.y += bb.y; v.z += bb.z; v.w += bb.w;
            }
            if (res) {
                float4 rr = *(const float4*)&res[(size_t)m * N + n];
                v.x += rr.x; v.y += rr.y; v.z += rr.z; v.w += rr.w;
            }
        }
        if (OUTMODE == 0) {
            *(float4*)&C[(size_t)m * N + n] = v;
        } else if (OUTMODE == 2) {
            bf16 hv[4], lv[4];
            bsplit(v.x, hv[0], lv[0]); bsplit(v.y, hv[1], lv[1]);
            bsplit(v.z, hv[2], lv[2]); bsplit(v.w, hv[3], lv[3]);
            *(uint2*)&Ch[(size_t)m * N + n] = *(uint2*)hv;
            *(uint2*)&Cl[(size_t)m * N + n] = *(uint2*)lv;
        } else {  // OUTMODE == 4
            int j0 = n >> 1;
            float g1a = v.x + bias[j0];
            float g2a = v.y + bias[DFF + j0];
            float g1b = v.z + bias[j0 + 1];
            float g2b = v.w + bias[DFF + j0 + 1];
            float ga = gelu_t(g1a) * g2a;
            float gb = gelu_t(g1b) * g2b;
            bf16 h0, l0, h1, l1;
            bsplit(ga, h0, l0); bsplit(gb, h1, l1);
            size_t o = (size_t)m * DFF + j0;
            *(unsigned*)&Ch[o] = pack2(h0, h1);
            *(unsigned*)&Cl[o] = pack2(l0, l1);
        }
    }
}

// ---------------- tensor-core flash attention (R10-proven: max-free, 3-term P*V) ----------------
#define LDQ 72
#define LDKV 72
#define LDP 72
#define LDSS 68
#define ATT_KV_STAGE (4*64*LDKV)
#define ATT_SMEM 182272
__global__ __launch_bounds__(256, 1) void attn_tc(
    const bf16* __restrict__ Qh_, const bf16* __restrict__ Ql_,
    const bf16* __restrict__ Kh_, const bf16* __restrict__ Kl_,
    const bf16* __restrict__ Vh_, const bf16* __restrict__ Vl_,
    bf16* __restrict__ Oh_, bf16* __restrict__ Ol_)
{
    extern __shared__ __align__(16) char smraw_[];
    bf16* sQh = (bf16*)smraw_;
    bf16* sQl = sQh + 128 * LDQ;
    bf16* sKV = sQl + 128 * LDQ;
    bf16* sPh = sKV + 2 * ATT_KV_STAGE;
    bf16* sPl = sPh + 128 * LDP;
    float* sS = (float*)(sPl + 128 * LDP);

    int tid = threadIdx.x;
    int warp = tid >> 5;
    int bh = blockIdx.y;
    int q0 = blockIdx.x * 128;
    size_t qoff = ((size_t)bh * SS + q0) * HDD;
    size_t bhoff = (size_t)bh * SS * HDD;

#pragma unroll
    for (int i = 0; i < 4; i++) {
        int idx = tid + i * 256;
        int r = idx >> 3, c8 = (idx & 7) * 8;
        *(uint4*)&sQh[r * LDQ + c8] = *(const uint4*)&Qh_[qoff + (size_t)r * HDD + c8];
        *(uint4*)&sQl[r * LDQ + c8] = *(const uint4*)&Ql_[qoff + (size_t)r * HDD + c8];
    }

    auto kv_issue = [&](int it, int st) {
        size_t koff = bhoff + (size_t)(it * 64) * HDD;
        bf16* kh = sKV + st * ATT_KV_STAGE;
        bf16* kl = kh + 64 * LDKV;
        bf16* vh = kl + 64 * LDKV;
        bf16* vl = vh + 64 * LDKV;
#pragma unroll
        for (int i = 0; i < 2; i++) {
            int idx = tid + i * 256;
            int rr = idx >> 3, c8 = (idx & 7) * 8;
            size_t g = koff + (size_t)rr * HDD + c8;
            __pipeline_memcpy_async(&kh[rr * LDKV + c8], &Kh_[g], 16);
            __pipeline_memcpy_async(&kl[rr * LDKV + c8], &Kl_[g], 16);
            __pipeline_memcpy_async(&vh[rr * LDKV + c8], &Vh_[g], 16);
            __pipeline_memcpy_async(&vl[rr * LDKV + c8], &Vl_[g], 16);
        }
        __pipeline_commit();
    };

    kv_issue(0, 0);
    kv_issue(1, 1);

    wmma::fragment<wmma::accumulator, 16, 16, 16, float> of[4];
#pragma unroll
    for (int j = 0; j < 4; j++) wmma::fill_fragment(of[j], 0.f);

    float l = 0.f;
    int r = tid >> 1, c0 = (tid & 1) * 32;
    const int niter = SS / 64;

    for (int it = 0; it < niter; it++) {
        int st = it & 1;
        __pipeline_wait_prior(1);
        __syncthreads();
        bf16* kh = sKV + st * ATT_KV_STAGE;
        bf16* kl = kh + 64 * LDKV;
        bf16* vh = kl + 64 * LDKV;
        bf16* vl = vh + 64 * LDKV;

        {
            wmma::fragment<wmma::accumulator, 16, 16, 16, float> sf[4];
#pragma unroll
            for (int j = 0; j < 4; j++) wmma::fill_fragment(sf[j], 0.f);
#pragma unroll
            for (int ks = 0; ks < 4; ks++) {
                wmma::fragment<wmma::matrix_a, 16, 16, 16, bf16, wmma::row_major> ah, al;
                wmma::load_matrix_sync(ah, &sQh[(warp * 16) * LDQ + ks * 16], LDQ);
                wmma::load_matrix_sync(al, &sQl[(warp * 16) * LDQ + ks * 16], LDQ);
#pragma unroll
                for (int j = 0; j < 4; j++) {
                    wmma::fragment<wmma::matrix_b, 16, 16, 16, bf16, wmma::col_major> bhf, blf;
                    wmma::load_matrix_sync(bhf, &kh[(j * 16) * LDKV + ks * 16], LDKV);
                    wmma::load_matrix_sync(blf, &kl[(j * 16) * LDKV + ks * 16], LDKV);
                    wmma::mma_sync(sf[j], ah, bhf, sf[j]);
                    wmma::mma_sync(sf[j], ah, blf, sf[j]);
                    wmma::mma_sync(sf[j], al, bhf, sf[j]);
                }
            }
#pragma unroll
            for (int j = 0; j < 4; j++)
                wmma::store_matrix_sync(&sS[(warp * 16) * LDSS + j * 16], sf[j], LDSS, wmma::mem_row_major);
        }
        __syncthreads();

        {
            const float* srow = sS + r * LDSS + c0;
            unsigned* ph = (unsigned*)&sPh[r * LDP + c0];
            unsigned* pl = (unsigned*)&sPl[r * LDP + c0];
            float sum = 0.f;
#pragma unroll
            for (int cc = 0; cc < 8; cc++) {
                float4 sv = *(const float4*)&srow[cc * 4];
                float p0 = __expf(sv.x), p1 = __expf(sv.y);
                float p2 = __expf(sv.z), p3 = __expf(sv.w);
                sum += (p0 + p1) + (p2 + p3);
                bf16 h0, l0, h1, l1, h2, l2, h3, l3;
                bsplit(p0, h0, l0); bsplit(p1, h1, l1);
                bsplit(p2, h2, l2); bsplit(p3, h3, l3);
                uint2 uh = { pack2(h0, h1), pack2(h2, h3) };
                uint2 ul = { pack2(l0, l1), pack2(l2, l3) };
                *(uint2*)&ph[cc * 2] = uh;
                *(uint2*)&pl[cc * 2] = ul;
            }
            l += sum;
        }
        __syncthreads();

        {
            wmma::fragment<wmma::matrix_a, 16, 16, 16, bf16, wmma::row_major> pah[4], pal[4];
#pragma unroll
            for (int ks = 0; ks < 4; ks++) {
                wmma::load_matrix_sync(pah[ks], &sPh[(warp * 16) * LDP + ks * 16], LDP);
                wmma::load_matrix_sync(pal[ks], &sPl[(warp * 16) * LDP + ks * 16], LDP);
            }
#pragma unroll
            for (int j = 0; j < 4; j++) {
#pragma unroll
                for (int ks = 0; ks < 4; ks++) {
                    wmma::fragment<wmma::matrix_b, 16, 16, 16, bf16, wmma::row_major> vbh, vbl;
                    wmma::load_matrix_sync(vbh, &vh[(ks * 16) * LDKV + j * 16], LDKV);
                    wmma::load_matrix_sync(vbl, &vl[(ks * 16) * LDKV + j * 16], LDKV);
                    wmma::mma_sync(of[j], pah[ks], vbh, of[j]);
                    wmma::mma_sync(of[j], pal[ks], vbh, of[j]);
                    wmma::mma_sync(of[j], pah[ks], vbl, of[j]);
                }
            }
        }
        __syncthreads();

        if (it + 2 < niter) kv_issue(it + 2, st);
        else __pipeline_commit();
    }

    l += __shfl_xor_sync(0xffffffffu, l, 1);
#pragma unroll
    for (int j = 0; j < 4; j++)
        wmma::store_matrix_sync(&sS[(warp * 16) * LDSS + j * 16], of[j], LDSS, wmma::mem_row_major);
    __syncthreads();

    int b = bh / HH, hd = bh % HH;
    float inv = 1.0f / l;
    size_t obase = ((size_t)(b * SS + q0 + r)) * DD + hd * HDD + c0;
    const float* orow = sS + r * LDSS + c0;
#pragma unroll
    for (int cc = 0; cc < 8; cc++) {
        float4 ov = *(const float4*)&orow[cc * 4];
        bf16 h0, l0, h1, l1, h2, l2, h3, l3;
        bsplit(ov.x * inv, h0, l0); bsplit(ov.y * inv, h1, l1);
        bsplit(ov.z * inv, h2, l2); bsplit(ov.w * inv, h3, l3);
        uint2 uh = { pack2(h0, h1), pack2(h2, h3) };
        uint2 ul = { pack2(l0, l1), pack2(l2, l3) };
        *(uint2*)&Oh_[obase + cc * 4] = uh;
        *(uint2*)&Ol_[obase + cc * 4] = ul;
    }
}

// ---------------- launch ----------------
extern "C" void kernel_launch(void* const* d_in, const int* in_sizes, int n_in,
                              void* d_out, int out_size) {
    const float* x    = (const float*)d_in[0];
    const float* anw  = (const float*)d_in[1];
    const float* anb  = (const float*)d_in[2];
    const float* Uq   = (const float*)d_in[3];
    const float* Vq   = (const float*)d_in[4];
    const float* bq   = (const float*)d_in[5];
    const float* Uk   = (const float*)d_in[6];
    const float* Vk   = (const float*)d_in[7];
    const float* bk   = (const float*)d_in[8];
    const float* Uv   = (const float*)d_in[9];
    const float* Vv   = (const float*)d_in[10];
    const float* bv   = (const float*)d_in[11];
    const float* Wo_w = (const float*)d_in[12];
    const float* Wo_b = (const float*)d_in[13];
    const float* mnw  = (const float*)d_in[14];
    const float* mnb  = (const float*)d_in[15];
    const float* Ui   = (const float*)d_in[16];
    const float* Vi   = (const float*)d_in[17];
    const float* bi   = (const float*)d_in[18];
    const float* Uo   = (const float*)d_in[19];
    const float* Vo   = (const float*)d_in[20];
    const float* bo   = (const float*)d_in[21];
    const float* cosT = (const float*)d_in[22];
    const float* sinT = (const float*)d_in[23];
    float* out = (float*)d_out;

    bf16 *hh,*hl,*weffh,*weffl,*woth,*wotl,*uih,*uil,*vih,*vil,*uoh,*uol,*voh,*vol;
    bf16 *qh,*ql,*kh,*kl,*vh,*vl,*oh,*ol,*h2h,*h2l,*t1h,*t1l,*gh,*gl,*t2h,*t2l;
    float *x1;
    cudaGetSymbolAddress((void**)&hh, g_hh);   cudaGetSymbolAddress((void**)&hl, g_hl);
    cudaGetSymbolAddress((void**)&weffh, g_weffh); cudaGetSymbolAddress((void**)&weffl, g_weffl);
    cudaGetSymbolAddress((void**)&woth, g_woth);   cudaGetSymbolAddress((void**)&wotl, g_wotl);
    cudaGetSymbolAddress((void**)&uih, g_uih); cudaGetSymbolAddress((void**)&uil, g_uil);
    cudaGetSymbolAddress((void**)&vih, g_vih); cudaGetSymbolAddress((void**)&vil, g_vil);
    cudaGetSymbolAddress((void**)&uoh, g_uoh); cudaGetSymbolAddress((void**)&uol, g_uol);
    cudaGetSymbolAddress((void**)&voh, g_voh); cudaGetSymbolAddress((void**)&vol, g_vol);
    cudaGetSymbolAddress((void**)&qh, g_qh); cudaGetSymbolAddress((void**)&ql, g_ql);
    cudaGetSymbolAddress((void**)&kh, g_kh); cudaGetSymbolAddress((void**)&kl, g_kl);
    cudaGetSymbolAddress((void**)&vh, g_vh); cudaGetSymbolAddress((void**)&vl, g_vl);
    cudaGetSymbolAddress((void**)&oh, g_oh); cudaGetSymbolAddress((void**)&ol, g_ol);
    cudaGetSymbolAddress((void**)&x1, g_x1);
    cudaGetSymbolAddress((void**)&h2h, g_h2h); cudaGetSymbolAddress((void**)&h2l, g_h2l);
    cudaGetSymbolAddress((void**)&t1h, g_t1h); cudaGetSymbolAddress((void**)&t1l, g_t1l);
    cudaGetSymbolAddress((void**)&gh, g_gh); cudaGetSymbolAddress((void**)&gl, g_gl);
    cudaGetSymbolAddress((void**)&t2h, g_t2h); cudaGetSymbolAddress((void**)&t2l, g_t2l);

    cudaFuncSetAttribute(attn_tc, cudaFuncAttributeMaxDynamicSharedMemorySize, ATT_SMEM);
    cudaFuncSetAttribute(gemm_qkv,   cudaFuncAttributeMaxDynamicSharedMemorySize, GEMM_SMEM);
    cudaFuncSetAttribute(gemm_bf3<0>, cudaFuncAttributeMaxDynamicSharedMemorySize, GEMM_SMEM);
    cudaFuncSetAttribute(gemm_bf3<2>, cudaFuncAttributeMaxDynamicSharedMemorySize, GEMM_SMEM);
    cudaFuncSetAttribute(gemm_bf3<4>, cudaFuncAttributeMaxDynamicSharedMemorySize, GEMM_SMEM);

    // 1. LN1
    ln_split<<<ROWS, 256>>>(x, anw, anb, hh, hl);
    // 2. weights -> hi/lo (weff + single fused split kernel)
    weff_kernel<<<(3 * DD * DD + 255) / 256, 256>>>(Uq, Vq, Uk, Vk, Uv, Vv, weffh, weffl);
    all_splits<<<(N_ALL + 255) / 256, 256>>>(Wo_w, Ui, Vi, Uo, Vo,
                                             woth, wotl, uih, uil, vih, vil, uoh, uol, voh, vol);
    // 3. fused Q/K/V projections (one launch)
    gemm_qkv<<<dim3(DD / 128, ROWS / 128, 3), 256, GEMM_SMEM>>>(
        hh, hl, weffh, weffl, bq, bk, bv, cosT, sinT, qh, ql, kh, kl, vh, vl);
    // 4. tensor-core attention (max-free flash, 3-term P*V)
    attn_tc<<<dim3(SS / 128, BB * HH), 256, ATT_SMEM>>>(qh, ql, kh, kl, vh, vl, oh, ol);
    // 5. x1 = x + o @ Wo^T + Wo_b
    gemm_bf3<0><<<dim3(DD / 128, ROWS / 128), 256, GEMM_SMEM>>>(oh, ol, woth, wotl, Wo_b, x, x1, nullptr, nullptr, ROWS, DD, DD);
    // 6. LN2
    ln_split<<<ROWS, 256>>>(x1, mnw, mnb, h2h, h2l);
    // 7. t1 = h2 @ Ui
    gemm_bf3<2><<<dim3(RF / 128, ROWS / 128), 256, GEMM_SMEM>>>(h2h, h2l, uih, uil, nullptr, nullptr, nullptr, t1h, t1l, ROWS, RF, DD);
    // 8. g = GEGLU(t1 @ ViP + biP) fused
    gemm_bf3<4><<<dim3(2 * DFF / 128, ROWS / 128), 256, GEMM_SMEM>>>(t1h, t1l, vih, vil, bi, nullptr, nullptr, gh, gl, ROWS, 2 * DFF, RF);
    // 9. t2 = g @ Uo
    gemm_bf3<2><<<dim3(RF / 128, ROWS / 128), 256, GEMM_SMEM>>>(gh, gl, uoh, uol, nullptr, nullptr, nullptr, t2h, t2l, ROWS, RF, DFF);
    // 10. out = x1 + t2 @ Vo + bo
    gemm_bf3<0><<<dim3(DD / 128, ROWS / 128), 256, GEMM_SMEM>>>(t2h, t2l, voh, vol, bo, x1, out, nullptr, nullptr, ROWS, DD, RF);
}

// round 14
// speedup vs baseline: 1.1238x; 1.0414x over previous
#include <cuda_runtime.h>
#include <cuda_bf16.h>
#include <cuda_pipeline.h>
#include <mma.h>
#include <math.h>
#include <cstdint>

using namespace nvcuda;

// ---------------- problem constants ----------------
#define BB 4
#define SS 2048
#define DD 768
#define HH 12
#define HDD 64
#define RA 32
#define RF 512
#define DFF 3072
#define ROWS (BB*SS)          // 8192

// ---------------- GEMM tile constants ----------------
#define BK 32
#define LDAs 40               // bf16 elems (80B rows, 16B aligned)
#define LDBs 136              // bf16 elems (272B rows)
#define A_TILE (128*LDAs)     // 5120
#define B_TILE (BK*LDBs)      // 4352
#define STAGE (2*A_TILE + 2*B_TILE)   // 18944 bf16
#define GEMM_SMEM (3*STAGE*2)         // 113664 bytes (3-stage)
#define LDC 132               // Csm floats: 128*132*4 = 67584 <= 113664

typedef __nv_bfloat16 bf16;

// ---------------- scratch ----------------
__device__ bf16  g_hh [ROWS*DD];
__device__ bf16  g_hl [ROWS*DD];
__device__ bf16  g_weffh[3*DD*DD];     // [which][k][n]
__device__ bf16  g_weffl[3*DD*DD];
__device__ bf16  g_woth[DD*DD];        // Wo^T [k][n]
__device__ bf16  g_wotl[DD*DD];
__device__ bf16  g_uih[DD*RF],  g_uil[DD*RF];
__device__ bf16  g_vih[RF*2*DFF], g_vil[RF*2*DFF];    // column-interleaved (g1,g2 pairs)
__device__ bf16  g_uoh[DFF*RF], g_uol[DFF*RF];
__device__ bf16  g_voh[RF*DD],  g_vol[RF*DD];
__device__ bf16  g_qh [ROWS*DD], g_ql[ROWS*DD];   // [B,H,S,HD] post-rope, q scaled
__device__ bf16  g_kh [ROWS*DD], g_kl[ROWS*DD];
__device__ bf16  g_vh [ROWS*DD], g_vl[ROWS*DD];
__device__ bf16  g_oh [ROWS*DD], g_ol[ROWS*DD];
__device__ float g_x1 [ROWS*DD];
__device__ bf16  g_h2h[ROWS*DD], g_h2l[ROWS*DD];
__device__ bf16  g_t1h[ROWS*RF], g_t1l[ROWS*RF];
__device__ bf16  g_gh [ROWS*DFF], g_gl[ROWS*DFF];
__device__ bf16  g_t2h[ROWS*RF], g_t2l[ROWS*RF];

__device__ __forceinline__ void bsplit(float a, bf16& h, bf16& l) {
    h = __float2bfloat16(a);
    l = __float2bfloat16(a - __bfloat162float(h));
}
__device__ __forceinline__ unsigned pack2(bf16 a, bf16 b) {
    __nv_bfloat162 t(a, b);
    return *(unsigned*)&t;
}
__device__ __forceinline__ float gelu_t(float x) {
    float t = 0.7978845608028654f * (x + 0.044715f * x * x * x);
    return 0.5f * x * (1.0f + tanhf(t));
}

// ---------------- layernorm -> bf16 hi/lo (warp-shuffle reduction) ----------------
__global__ __launch_bounds__(256) void ln_split(const float* __restrict__ x,
                                                const float* __restrict__ w,
                                                const float* __restrict__ b,
                                                bf16* __restrict__ oh,
                                                bf16* __restrict__ ol) {
    int row = blockIdx.x;
    const float* xr = x + (size_t)row * DD;
    float vals[3];
    float s = 0.f, s2 = 0.f;
    int tid = threadIdx.x;
#pragma unroll
    for (int i = 0; i < 3; i++) {
        float v = xr[tid + i * 256];
        vals[i] = v; s += v; s2 += v * v;
    }
#pragma unroll
    for (int off = 16; off > 0; off >>= 1) {
        s  += __shfl_xor_sync(0xffffffffu, s,  off);
        s2 += __shfl_xor_sync(0xffffffffu, s2, off);
    }
    __shared__ float sh[8], sh2[8];
    int warp = tid >> 5, lane = tid & 31;
    if (lane == 0) { sh[warp] = s; sh2[warp] = s2; }
    __syncthreads();
    float ts = 0.f, ts2 = 0.f;
#pragma unroll
    for (int i = 0; i < 8; i++) { ts += sh[i]; ts2 += sh2[i]; }
    float mean = ts * (1.0f / DD);
    float var  = ts2 * (1.0f / DD) - mean * mean;
    float rstd = rsqrtf(var + 1e-6f);
#pragma unroll
    for (int i = 0; i < 3; i++) {
        int c = tid + i * 256;
        float y = (vals[i] - mean) * rstd * w[c] + b[c];
        bsplit(y, oh[(size_t)row * DD + c], ol[(size_t)row * DD + c]);
    }
}

// ---------------- effective weight -> hi/lo ([k][n]) ----------------
__global__ __launch_bounds__(256) void weff_kernel(const float* __restrict__ Uq, const float* __restrict__ Vq,
                                                   const float* __restrict__ Uk, const float* __restrict__ Vk,
                                                   const float* __restrict__ Uv, const float* __restrict__ Vv,
                                                   bf16* __restrict__ wh, bf16* __restrict__ wl) {
    int idx = blockIdx.x * 256 + threadIdx.x;
    if (idx >= 3 * DD * DD) return;
    int which = idx / (DD * DD);
    int rem = idx % (DD * DD);
    int d = rem / DD, j = rem % DD;
    int hh = j >> 6, e = j & 63;
    const float* U = (which == 0) ? Uq : (which == 1) ? Uk : Uv;
    const float* V = (which == 0) ? Vq : (which == 1) ? Vk : Vv;
    const float* Uhd = U + ((size_t)hh * DD + d) * RA;
    const float* Vh  = V + (size_t)hh * RA * HDD + e;
    float acc = 0.f;
#pragma unroll
    for (int r = 0; r < RA; r++) acc += Uhd[r] * Vh[r * HDD];
    bsplit(acc, wh[idx], wl[idx]);
}

// ---------------- all weight splits in ONE kernel (range dispatch) ----------------
#define N_WOT (DD*DD)
#define N_UI  (DD*RF)
#define N_VI  (RF*2*DFF)
#define N_UO  (DFF*RF)
#define N_VO  (RF*DD)
#define N_ALL (N_WOT+N_UI+N_VI+N_UO+N_VO)
__global__ __launch_bounds__(256) void all_splits(
    const float* __restrict__ Wo, const float* __restrict__ Ui, const float* __restrict__ Vi,
    const float* __restrict__ Uo, const float* __restrict__ Vo,
    bf16* __restrict__ woth, bf16* __restrict__ wotl,
    bf16* __restrict__ uih,  bf16* __restrict__ uil,
    bf16* __restrict__ vih,  bf16* __restrict__ vil,
    bf16* __restrict__ uoh,  bf16* __restrict__ uol,
    bf16* __restrict__ voh,  bf16* __restrict__ vol)
{
    int idx = blockIdx.x * 256 + threadIdx.x;
    if (idx >= N_ALL) return;
    if (idx < N_WOT) {
        int k = idx / DD, n = idx % DD;                 // Wo^T
        bsplit(Wo[(size_t)n * DD + k], woth[idx], wotl[idx]);
        return;
    }
    idx -= N_WOT;
    if (idx < N_UI) { bsplit(Ui[idx], uih[idx], uil[idx]); return; }
    idx -= N_UI;
    if (idx < N_VI) {                                    // Vi perm-interleave
        int k = idx / (2 * DFF), n = idx % (2 * DFF);
        int j = n >> 1;
        int srcn = (n & 1) ? (DFF + j) : j;
        bsplit(Vi[(size_t)k * (2 * DFF) + srcn], vih[idx], vil[idx]);
        return;
    }
    idx -= N_VI;
    if (idx < N_UO) { bsplit(Uo[idx], uoh[idx], uol[idx]); return; }
    idx -= N_UO;
    bsplit(Vo[idx], voh[idx], vol[idx]);
}

// ---------------- shared GEMM mainloop (3-stage, single barrier, correct order) ----------------
struct GemmCore {
    wmma::fragment<wmma::accumulator, 16, 16, 16, float> cf[4][2];
};

__device__ __forceinline__ void gemm_mainloop(
    GemmCore& gc, bf16* smb, int tid, int warp_m, int warp_n,
    const bf16* Agh, const bf16* Agl, const bf16* Bgh, const bf16* Bgl,
    int m0, int n0, int N, int K)
{
    auto issue = [&](int c, int st) {
        int k0 = c * BK;
        bf16* sAh = smb + st * STAGE;
        bf16* sAl = sAh + A_TILE;
        bf16* sBh = sAl + A_TILE;
        bf16* sBl = sBh + B_TILE;
#pragma unroll
        for (int i = 0; i < 2; i++) {
            int t = tid + i * 256;
            int ar = t >> 2;
            int ac = (t & 3) * 8;
            size_t ag = (size_t)(m0 + ar) * K + k0 + ac;
            __pipeline_memcpy_async(&sAh[ar * LDAs + ac], &Agh[ag], 16);
            __pipeline_memcpy_async(&sAl[ar * LDAs + ac], &Agl[ag], 16);
            int br = t >> 4;
            int bc = (t & 15) * 8;
            size_t bg = (size_t)(k0 + br) * N + n0 + bc;
            __pipeline_memcpy_async(&sBh[br * LDBs + bc], &Bgh[bg], 16);
            __pipeline_memcpy_async(&sBl[br * LDBs + bc], &Bgl[bg], 16);
        }
    };

#pragma unroll
    for (int i = 0; i < 4; i++)
#pragma unroll
        for (int j = 0; j < 2; j++) wmma::fill_fragment(gc.cf[i][j], 0.0f);

    int nch = K / BK;
    issue(0, 0); __pipeline_commit();   // g0
    issue(1, 1); __pipeline_commit();   // g1

    int st = 0;   // stage of chunk c
    int stn = 2;  // stage of chunk c+2
    for (int c = 0; c < nch; c++) {
        __pipeline_wait_prior(1);       // chunk c's group complete (own thread)
        __syncthreads();                // visibility to all threads; all warps past compute(c-1)
        bf16* sAh = smb + st * STAGE;
        bf16* sAl = sAh + A_TILE;
        bf16* sBh = sAl + A_TILE;
        bf16* sBl = sBh + B_TILE;
#pragma unroll
        for (int ks = 0; ks < 2; ks++) {
            wmma::fragment<wmma::matrix_b, 16, 16, 16, bf16, wmma::row_major> bh[2], bl[2];
#pragma unroll
            for (int j = 0; j < 2; j++) {
                wmma::load_matrix_sync(bh[j], &sBh[(ks * 16) * LDBs + warp_n * 32 + j * 16], LDBs);
                wmma::load_matrix_sync(bl[j], &sBl[(ks * 16) * LDBs + warp_n * 32 + j * 16], LDBs);
            }
#pragma unroll
            for (int i = 0; i < 4; i++) {
                wmma::fragment<wmma::matrix_a, 16, 16, 16, bf16, wmma::row_major> ah, al;
                wmma::load_matrix_sync(ah, &sAh[(warp_m * 64 + i * 16) * LDAs + ks * 16], LDAs);
                wmma::load_matrix_sync(al, &sAl[(warp_m * 64 + i * 16) * LDAs + ks * 16], LDAs);
#pragma unroll
                for (int j = 0; j < 2; j++) {
                    wmma::mma_sync(gc.cf[i][j], ah, bh[j], gc.cf[i][j]);
                    wmma::mma_sync(gc.cf[i][j], ah, bl[j], gc.cf[i][j]);
                    wmma::mma_sync(gc.cf[i][j], al, bh[j], gc.cf[i][j]);
                }
            }
        }
        if (c + 2 < nch) issue(c + 2, stn);   // stage (c+2)%3 == (c-1)%3, safe per barrier
        __pipeline_commit();                  // unconditional: exact group counting
        st  = (st  == 2) ? 0 : st + 1;
        stn = (stn == 2) ? 0 : stn + 1;
    }
    __syncthreads();   // protect Csm epilogue aliasing the stages
}

__device__ __forceinline__ void gemm_store_frags(GemmCore& gc, float* Csm, int warp_m, int warp_n) {
#pragma unroll
    for (int i = 0; i < 4; i++)
#pragma unroll
        for (int j = 0; j < 2; j++)
            wmma::store_matrix_sync(&Csm[(warp_m * 64 + i * 16) * LDC + warp_n * 32 + j * 16],
                                    gc.cf[i][j], LDC, wmma::mem_row_major);
}

// ---------------- fused QKV GEMM (z: 0=Q rope*0.125, 1=K rope*1, 2=V split scatter) ----------------
__global__ __launch_bounds__(256, 2) void gemm_qkv(
    const bf16* __restrict__ Agh, const bf16* __restrict__ Agl,
    const bf16* __restrict__ Wh, const bf16* __restrict__ Wl,
    const float* __restrict__ bq, const float* __restrict__ bk, const float* __restrict__ bv,
    const float* __restrict__ cosT, const float* __restrict__ sinT,
    bf16* __restrict__ Qh, bf16* __restrict__ Ql,
    bf16* __restrict__ Kh, bf16* __restrict__ Kl,
    bf16* __restrict__ Vh, bf16* __restrict__ Vl)
{
    extern __shared__ __align__(16) char smraw[];
    bf16* smb = (bf16*)smraw;
    int tid = threadIdx.x;
    int wid = tid >> 5;
    int warp_m = wid >> 2, warp_n = wid & 3;
    int m0 = blockIdx.y * 128, n0 = blockIdx.x * 128;
    int z = blockIdx.z;

    const bf16* Bgh = Wh + (size_t)z * DD * DD;
    const bf16* Bgl = Wl + (size_t)z * DD * DD;
    const float* bias = (z == 0) ? bq : (z == 1) ? bk : bv;
    float scale = (z == 0) ? 0.125f : 1.0f;

    GemmCore gc;
    gemm_mainloop(gc, smb, tid, warp_m, warp_n, Agh, Agl, Bgh, Bgl, m0, n0, DD, DD);

    float* Csm = (float*)smraw;
    gemm_store_frags(gc, Csm, warp_m, warp_n);
    __syncthreads();

#pragma unroll
    for (int it = 0; it < 16; it++) {
        int idx = tid + it * 256;
        int r = idx >> 5;
        int c4 = (idx & 31) << 2;
        float4 v = *(const float4*)&Csm[r * LDC + c4];
        int m = m0 + r, n = n0 + c4;
        int e = n & 63;
        int s = m & 2047;
        int b = m >> 11, head = n >> 6;
        size_t o = (((size_t)b * HH + head) * SS + s) * HDD + e;
        if (z == 2) {
            float4 bb = *(const float4*)&bias[n];
            v.x += bb.x; v.y += bb.y; v.z += bb.z; v.w += bb.w;
            bf16 hv[4], lv[4];
            bsplit(v.x, hv[0], lv[0]); bsplit(v.y, hv[1], lv[1]);
            bsplit(v.z, hv[2], lv[2]); bsplit(v.w, hv[3], lv[3]);
            *(uint2*)&Vh[o] = *(uint2*)hv;
            *(uint2*)&Vl[o] = *(uint2*)lv;
        } else {
            float4 p = *(const float4*)&Csm[r * LDC + (c4 ^ 32)];
            float4 bb = *(const float4*)&bias[n];
            v.x += bb.x; v.y += bb.y; v.z += bb.z; v.w += bb.w;
            float4 pb = *(const float4*)&bias[n ^ 32];
            p.x += pb.x; p.y += pb.y; p.z += pb.z; p.w += pb.w;
            float4 cs = *(const float4*)&cosT[s * HDD + e];
            float4 sn = *(const float4*)&sinT[s * HDD + e];
            float4 o4;
            if (e < 32) {
                o4.x = v.x * cs.x - p.x * sn.x; o4.y = v.y * cs.y - p.y * sn.y;
                o4.z = v.z * cs.z - p.z * sn.z; o4.w = v.w * cs.w - p.w * sn.w;
            } else {
                o4.x = v.x * cs.x + p.x * sn.x; o4.y = v.y * cs.y + p.y * sn.y;
                o4.z = v.z * cs.z + p.z * sn.z; o4.w = v.w * cs.w + p.w * sn.w;
            }
            o4.x *= scale; o4.y *= scale; o4.z *= scale; o4.w *= scale;
            bf16* Ch = (z == 0) ? Qh : Kh;
            bf16* Cl = (z == 0) ? Ql : Kl;
            bf16 hv[4], lv[4];
            bsplit(o4.x, hv[0], lv[0]); bsplit(o4.y, hv[1], lv[1]);
            bsplit(o4.z, hv[2], lv[2]); bsplit(o4.w, hv[3], lv[3]);
            *(uint2*)&Ch[o] = *(uint2*)hv;
            *(uint2*)&Cl[o] = *(uint2*)lv;
        }
    }
}

// ---------------- generic bf16x3 GEMM (OUTMODE: 0 fp32+bias+res; 2 split; 4 GEGLU) ----------------
template<int OUTMODE>
__global__ __launch_bounds__(256, 2) void gemm_bf3(
    const bf16* __restrict__ Agh, const bf16* __restrict__ Agl,
    const bf16* __restrict__ Bgh, const bf16* __restrict__ Bgl,
    const float* __restrict__ bias, const float* __restrict__ res,
    float* __restrict__ C, bf16* __restrict__ Ch, bf16* __restrict__ Cl,
    int M, int N, int K)
{
    extern __shared__ __align__(16) char smraw[];
    bf16* smb = (bf16*)smraw;
    int tid = threadIdx.x;
    int wid = tid >> 5;
    int warp_m = wid >> 2, warp_n = wid & 3;
    int m0 = blockIdx.y * 128, n0 = blockIdx.x * 128;

    GemmCore gc;
    gemm_mainloop(gc, smb, tid, warp_m, warp_n, Agh, Agl, Bgh, Bgl, m0, n0, N, K);

    float* Csm = (float*)smraw;
    gemm_store_frags(gc, Csm, warp_m, warp_n);
    __syncthreads();

#pragma unroll
    for (int it = 0; it < 16; it++) {
        int idx = tid + it * 256;
        int r = idx >> 5;
        int c4 = (idx & 31) << 2;
        float4 v = *(const float4*)&Csm[r * LDC + c4];
        int m = m0 + r, n = n0 + c4;
        if (OUTMODE != 4) {
            if (bias) {
                float4 bb = *(const float4*)&bias[n];
                v.x += bb.x; v.y += bb.y; v.z += bb.z; v.w += bb.w;
            }
            if (res) {
                float4 rr = *(const float4*)&res[(size_t)m * N + n];
                v.x += rr.x; v.y += rr.y; v.z += rr.z; v.w += rr.w;
            }
        }
        if (OUTMODE == 0) {
            *(float4*)&C[(size_t)m * N + n] = v;
        } else if (OUTMODE == 2) {
            bf16 hv[4], lv[4];
            bsplit(v.x, hv[0], lv[0]); bsplit(v.y, hv[1], lv[1]);
            bsplit(v.z, hv[2], lv[2]); bsplit(v.w, hv[3], lv[3]);
            *(uint2*)&Ch[(size_t)m * N + n] = *(uint2*)hv;
            *(uint2*)&Cl[(size_t)m * N + n] = *(uint2*)lv;
        } else {  // OUTMODE == 4
            int j0 = n >> 1;
            float g1a = v.x + bias[j0];
            float g2a = v.y + bias[DFF + j0];
            float g1b = v.z + bias[j0 + 1];
            float g2b = v.w + bias[DFF + j0 + 1];
            float ga = gelu_t(g1a) * g2a;
            float gb = gelu_t(g1b) * g2b;
            bf16 h0, l0, h1, l1;
            bsplit(ga, h0, l0); bsplit(gb, h1, l1);
            size_t o = (size_t)m * DFF + j0;
            *(unsigned*)&Ch[o] = pack2(h0, h1);
            *(unsigned*)&Cl[o] = pack2(l0, l1);
        }
    }
}

// ---------------- tensor-core flash attention (R10-proven: max-free, 3-term P*V) ----------------
#define LDQ 72
#define LDKV 72
#define LDP 72
#define LDSS 68
#define ATT_KV_STAGE (4*64*LDKV)
#define ATT_SMEM 182272
__global__ __launch_bounds__(256, 1) void attn_tc(
    const bf16* __restrict__ Qh_, const bf16* __restrict__ Ql_,
    const bf16* __restrict__ Kh_, const bf16* __restrict__ Kl_,
    const bf16* __restrict__ Vh_, const bf16* __restrict__ Vl_,
    bf16* __restrict__ Oh_, bf16* __restrict__ Ol_)
{
    extern __shared__ __align__(16) char smraw_[];
    bf16* sQh = (bf16*)smraw_;
    bf16* sQl = sQh + 128 * LDQ;
    bf16* sKV = sQl + 128 * LDQ;
    bf16* sPh = sKV + 2 * ATT_KV_STAGE;
    bf16* sPl = sPh + 128 * LDP;
    float* sS = (float*)(sPl + 128 * LDP);

    int tid = threadIdx.x;
    int warp = tid >> 5;
    int bh = blockIdx.y;
    int q0 = blockIdx.x * 128;
    size_t qoff = ((size_t)bh * SS + q0) * HDD;
    size_t bhoff = (size_t)bh * SS * HDD;

#pragma unroll
    for (int i = 0; i < 4; i++) {
        int idx = tid + i * 256;
        int r = idx >> 3, c8 = (idx & 7) * 8;
        *(uint4*)&sQh[r * LDQ + c8] = *(const uint4*)&Qh_[qoff + (size_t)r * HDD + c8];
        *(uint4*)&sQl[r * LDQ + c8] = *(const uint4*)&Ql_[qoff + (size_t)r * HDD + c8];
    }

    auto kv_issue = [&](int it, int st) {
        size_t koff = bhoff + (size_t)(it * 64) * HDD;
        bf16* kh = sKV + st * ATT_KV_STAGE;
        bf16* kl = kh + 64 * LDKV;
        bf16* vh = kl + 64 * LDKV;
        bf16* vl = vh + 64 * LDKV;
#pragma unroll
        for (int i = 0; i < 2; i++) {
            int idx = tid + i * 256;
            int rr = idx >> 3, c8 = (idx & 7) * 8;
            size_t g = koff + (size_t)rr * HDD + c8;
            __pipeline_memcpy_async(&kh[rr * LDKV + c8], &Kh_[g], 16);
            __pipeline_memcpy_async(&kl[rr * LDKV + c8], &Kl_[g], 16);
            __pipeline_memcpy_async(&vh[rr * LDKV + c8], &Vh_[g], 16);
            __pipeline_memcpy_async(&vl[rr * LDKV + c8], &Vl_[g], 16);
        }
        __pipeline_commit();
    };

    kv_issue(0, 0);
    kv_issue(1, 1);

    wmma::fragment<wmma::accumulator, 16, 16, 16, float> of[4];
#pragma unroll
    for (int j = 0; j < 4; j++) wmma::fill_fragment(of[j], 0.f);

    float l = 0.f;
    int r = tid >> 1, c0 = (tid & 1) * 32;
    const int niter = SS / 64;

    for (int it = 0; it < niter; it++) {
        int st = it & 1;
        __pipeline_wait_prior(1);
        __syncthreads();
        bf16* kh = sKV + st * ATT_KV_STAGE;
        bf16* kl = kh + 64 * LDKV;
        bf16* vh = kl + 64 * LDKV;
        bf16* vl = vh + 64 * LDKV;

        {
            wmma::fragment<wmma::accumulator, 16, 16, 16, float> sf[4];
#pragma unroll
            for (int j = 0; j < 4; j++) wmma::fill_fragment(sf[j], 0.f);
#pragma unroll
            for (int ks = 0; ks < 4; ks++) {
                wmma::fragment<wmma::matrix_a, 16, 16, 16, bf16, wmma::row_major> ah, al;
                wmma::load_matrix_sync(ah, &sQh[(warp * 16) * LDQ + ks * 16], LDQ);
                wmma::load_matrix_sync(al, &sQl[(warp * 16) * LDQ + ks * 16], LDQ);
#pragma unroll
                for (int j = 0; j < 4; j++) {
                    wmma::fragment<wmma::matrix_b, 16, 16, 16, bf16, wmma::col_major> bhf, blf;
                    wmma::load_matrix_sync(bhf, &kh[(j * 16) * LDKV + ks * 16], LDKV);
                    wmma::load_matrix_sync(blf, &kl[(j * 16) * LDKV + ks * 16], LDKV);
                    wmma::mma_sync(sf[j], ah, bhf, sf[j]);
                    wmma::mma_sync(sf[j], ah, blf, sf[j]);
                    wmma::mma_sync(sf[j], al, bhf, sf[j]);
                }
            }
#pragma unroll
            for (int j = 0; j < 4; j++)
                wmma::store_matrix_sync(&sS[(warp * 16) * LDSS + j * 16], sf[j], LDSS, wmma::mem_row_major);
        }
        __syncthreads();

        {
            const float* srow = sS + r * LDSS + c0;
            unsigned* ph = (unsigned*)&sPh[r * LDP + c0];
            unsigned* pl = (unsigned*)&sPl[r * LDP + c0];
            float sum = 0.f;
#pragma unroll
            for (int cc = 0; cc < 8; cc++) {
                float4 sv = *(const float4*)&srow[cc * 4];
                float p0 = __expf(sv.x), p1 = __expf(sv.y);
                float p2 = __expf(sv.z), p3 = __expf(sv.w);
                sum += (p0 + p1) + (p2 + p3);
                bf16 h0, l0, h1, l1, h2, l2, h3, l3;
                bsplit(p0, h0, l0); bsplit(p1, h1, l1);
                bsplit(p2, h2, l2); bsplit(p3, h3, l3);
                uint2 uh = { pack2(h0, h1), pack2(h2, h3) };
                uint2 ul = { pack2(l0, l1), pack2(l2, l3) };
                *(uint2*)&ph[cc * 2] = uh;
                *(uint2*)&pl[cc * 2] = ul;
            }
            l += sum;
        }
        __syncthreads();

        {
            wmma::fragment<wmma::matrix_a, 16, 16, 16, bf16, wmma::row_major> pah[4], pal[4];
#pragma unroll
            for (int ks = 0; ks < 4; ks++) {
                wmma::load_matrix_sync(pah[ks], &sPh[(warp * 16) * LDP + ks * 16], LDP);
                wmma::load_matrix_sync(pal[ks], &sPl[(warp * 16) * LDP + ks * 16], LDP);
            }
#pragma unroll
            for (int j = 0; j < 4; j++) {
#pragma unroll
                for (int ks = 0; ks < 4; ks++) {
                    wmma::fragment<wmma::matrix_b, 16, 16, 16, bf16, wmma::row_major> vbh, vbl;
                    wmma::load_matrix_sync(vbh, &vh[(ks * 16) * LDKV + j * 16], LDKV);
                    wmma::load_matrix_sync(vbl, &vl[(ks * 16) * LDKV + j * 16], LDKV);
                    wmma::mma_sync(of[j], pah[ks], vbh, of[j]);
                    wmma::mma_sync(of[j], pal[ks], vbh, of[j]);
                    wmma::mma_sync(of[j], pah[ks], vbl, of[j]);
                }
            }
        }
        __syncthreads();

        if (it + 2 < niter) kv_issue(it + 2, st);
        else __pipeline_commit();
    }

    l += __shfl_xor_sync(0xffffffffu, l, 1);
#pragma unroll
    for (int j = 0; j < 4; j++)
        wmma::store_matrix_sync(&sS[(warp * 16) * LDSS + j * 16], of[j], LDSS, wmma::mem_row_major);
    __syncthreads();

    int b = bh / HH, hd = bh % HH;
    float inv = 1.0f / l;
    size_t obase = ((size_t)(b * SS + q0 + r)) * DD + hd * HDD + c0;
    const float* orow = sS + r * LDSS + c0;
#pragma unroll
    for (int cc = 0; cc < 8; cc++) {
        float4 ov = *(const float4*)&orow[cc * 4];
        bf16 h0, l0, h1, l1, h2, l2, h3, l3;
        bsplit(ov.x * inv, h0, l0); bsplit(ov.y * inv, h1, l1);
        bsplit(ov.z * inv, h2, l2); bsplit(ov.w * inv, h3, l3);
        uint2 uh = { pack2(h0, h1), pack2(h2, h3) };
        uint2 ul = { pack2(l0, l1), pack2(l2, l3) };
        *(uint2*)&Oh_[obase + cc * 4] = uh;
        *(uint2*)&Ol_[obase + cc * 4] = ul;
    }
}

// ---------------- launch ----------------
extern "C" void kernel_launch(void* const* d_in, const int* in_sizes, int n_in,
                              void* d_out, int out_size) {
    const float* x    = (const float*)d_in[0];
    const float* anw  = (const float*)d_in[1];
    const float* anb  = (const float*)d_in[2];
    const float* Uq   = (const float*)d_in[3];
    const float* Vq   = (const float*)d_in[4];
    const float* bq   = (const float*)d_in[5];
    const float* Uk   = (const float*)d_in[6];
    const float* Vk   = (const float*)d_in[7];
    const float* bk   = (const float*)d_in[8];
    const float* Uv   = (const float*)d_in[9];
    const float* Vv   = (const float*)d_in[10];
    const float* bv   = (const float*)d_in[11];
    const float* Wo_w = (const float*)d_in[12];
    const float* Wo_b = (const float*)d_in[13];
    const float* mnw  = (const float*)d_in[14];
    const float* mnb  = (const float*)d_in[15];
    const float* Ui   = (const float*)d_in[16];
    const float* Vi   = (const float*)d_in[17];
    const float* bi   = (const float*)d_in[18];
    const float* Uo   = (const float*)d_in[19];
    const float* Vo   = (const float*)d_in[20];
    const float* bo   = (const float*)d_in[21];
    const float* cosT = (const float*)d_in[22];
    const float* sinT = (const float*)d_in[23];
    float* out = (float*)d_out;

    bf16 *hh,*hl,*weffh,*weffl,*woth,*wotl,*uih,*uil,*vih,*vil,*uoh,*uol,*voh,*vol;
    bf16 *qh,*ql,*kh,*kl,*vh,*vl,*oh,*ol,*h2h,*h2l,*t1h,*t1l,*gh,*gl,*t2h,*t2l;
    float *x1;
    cudaGetSymbolAddress((void**)&hh, g_hh);   cudaGetSymbolAddress((void**)&hl, g_hl);
    cudaGetSymbolAddress((void**)&weffh, g_weffh); cudaGetSymbolAddress((void**)&weffl, g_weffl);
    cudaGetSymbolAddress((void**)&woth, g_woth);   cudaGetSymbolAddress((void**)&wotl, g_wotl);
    cudaGetSymbolAddress((void**)&uih, g_uih); cudaGetSymbolAddress((void**)&uil, g_uil);
    cudaGetSymbolAddress((void**)&vih, g_vih); cudaGetSymbolAddress((void**)&vil, g_vil);
    cudaGetSymbolAddress((void**)&uoh, g_uoh); cudaGetSymbolAddress((void**)&uol, g_uol);
    cudaGetSymbolAddress((void**)&voh, g_voh); cudaGetSymbolAddress((void**)&vol, g_vol);
    cudaGetSymbolAddress((void**)&qh, g_qh); cudaGetSymbolAddress((void**)&ql, g_ql);
    cudaGetSymbolAddress((void**)&kh, g_kh); cudaGetSymbolAddress((void**)&kl, g_kl);
    cudaGetSymbolAddress((void**)&vh, g_vh); cudaGetSymbolAddress((void**)&vl, g_vl);
    cudaGetSymbolAddress((void**)&oh, g_oh); cudaGetSymbolAddress((void**)&ol, g_ol);
    cudaGetSymbolAddress((void**)&x1, g_x1);
    cudaGetSymbolAddress((void**)&h2h, g_h2h); cudaGetSymbolAddress((void**)&h2l, g_h2l);
    cudaGetSymbolAddress((void**)&t1h, g_t1h); cudaGetSymbolAddress((void**)&t1l, g_t1l);
    cudaGetSymbolAddress((void**)&gh, g_gh); cudaGetSymbolAddress((void**)&gl, g_gl);
    cudaGetSymbolAddress((void**)&t2h, g_t2h); cudaGetSymbolAddress((void**)&t2l, g_t2l);

    cudaFuncSetAttribute(attn_tc, cudaFuncAttributeMaxDynamicSharedMemorySize, ATT_SMEM);
    cudaFuncSetAttribute(gemm_qkv,   cudaFuncAttributeMaxDynamicSharedMemorySize, GEMM_SMEM);
    cudaFuncSetAttribute(gemm_bf3<0>, cudaFuncAttributeMaxDynamicSharedMemorySize, GEMM_SMEM);
    cudaFuncSetAttribute(gemm_bf3<2>, cudaFuncAttributeMaxDynamicSharedMemorySize, GEMM_SMEM);
    cudaFuncSetAttribute(gemm_bf3<4>, cudaFuncAttributeMaxDynamicSharedMemorySize, GEMM_SMEM);

    // 1. LN1
    ln_split<<<ROWS, 256>>>(x, anw, anb, hh, hl);
    // 2. weights -> hi/lo (weff + single fused split kernel)
    weff_kernel<<<(3 * DD * DD + 255) / 256, 256>>>(Uq, Vq, Uk, Vk, Uv, Vv, weffh, weffl);
    all_splits<<<(N_ALL + 255) / 256, 256>>>(Wo_w, Ui, Vi, Uo, Vo,
                                             woth, wotl, uih, uil, vih, vil, uoh, uol, voh, vol);
    // 3. fused Q/K/V projections (one launch)
    gemm_qkv<<<dim3(DD / 128, ROWS / 128, 3), 256, GEMM_SMEM>>>(
        hh, hl, weffh, weffl, bq, bk, bv, cosT, sinT, qh, ql, kh, kl, vh, vl);
    // 4. tensor-core attention (max-free flash, 3-term P*V)
    attn_tc<<<dim3(SS / 128, BB * HH), 256, ATT_SMEM>>>(qh, ql, kh, kl, vh, vl, oh, ol);
    // 5. x1 = x + o @ Wo^T + Wo_b
    gemm_bf3<0><<<dim3(DD / 128, ROWS / 128), 256, GEMM_SMEM>>>(oh, ol, woth, wotl, Wo_b, x, x1, nullptr, nullptr, ROWS, DD, DD);
    // 6. LN2
    ln_split<<<ROWS, 256>>>(x1, mnw, mnb, h2h, h2l);
    // 7. t1 = h2 @ Ui
    gemm_bf3<2><<<dim3(RF / 128, ROWS / 128), 256, GEMM_SMEM>>>(h2h, h2l, uih, uil, nullptr, nullptr, nullptr, t1h, t1l, ROWS, RF, DD);
    // 8. g = GEGLU(t1 @ ViP + biP) fused
    gemm_bf3<4><<<dim3(2 * DFF / 128, ROWS / 128), 256, GEMM_SMEM>>>(t1h, t1l, vih, vil, bi, nullptr, nullptr, gh, gl, ROWS, 2 * DFF, RF);
    // 9. t2 = g @ Uo
    gemm_bf3<2><<<dim3(RF / 128, ROWS / 128), 256, GEMM_SMEM>>>(gh, gl, uoh, uol, nullptr, nullptr, nullptr, t2h, t2l, ROWS, RF, DFF);
    // 10. out = x1 + t2 @ Vo + bo
    gemm_bf3<0><<<dim3(DD / 128, ROWS / 128), 256, GEMM_SMEM>>>(t2h, t2l, voh, vol, bo, x1, out, nullptr, nullptr, ROWS, DD, RF);
}

// round 15
// speedup vs baseline: 1.1340x; 1.0091x over previous
#include <cuda_runtime.h>
#include <cuda_bf16.h>
#include <cuda_pipeline.h>
#include <mma.h>
#include <math.h>
#include <cstdint>

using namespace nvcuda;

// ---------------- problem constants ----------------
#define BB 4
#define SS 2048
#define DD 768
#define HH 12
#define HDD 64
#define RA 32
#define RF 512
#define DFF 3072
#define ROWS (BB*SS)          // 8192

// ---------------- GEMM tile constants ----------------
#define BK 32
#define LDAs 40               // bf16 elems (80B rows, 16B aligned)
#define LDBs 136              // bf16 elems (272B rows)
#define A_TILE (128*LDAs)     // 5120
#define B_TILE (BK*LDBs)      // 4352
#define STAGE (2*A_TILE + 2*B_TILE)   // 18944 bf16
#define GEMM_SMEM (3*STAGE*2)         // 113664 bytes (3-stage)
#define LDC 132

typedef __nv_bfloat16 bf16;

// ---------------- scratch ----------------
__device__ bf16  g_hh [ROWS*DD];
__device__ bf16  g_hl [ROWS*DD];
__device__ bf16  g_weffh[3*DD*DD];     // [which][k][n]
__device__ bf16  g_weffl[3*DD*DD];
__device__ bf16  g_woth[DD*DD];        // Wo^T [k][n]
__device__ bf16  g_wotl[DD*DD];
__device__ bf16  g_uih[DD*RF],  g_uil[DD*RF];
__device__ bf16  g_vih[RF*2*DFF], g_vil[RF*2*DFF];    // column-interleaved (g1,g2 pairs)
__device__ bf16  g_uoh[DFF*RF], g_uol[DFF*RF];
__device__ bf16  g_voh[RF*DD],  g_vol[RF*DD];
__device__ bf16  g_qh [ROWS*DD], g_ql[ROWS*DD];   // [B,H,S,HD] post-rope, q scaled
__device__ bf16  g_kh [ROWS*DD], g_kl[ROWS*DD];
__device__ bf16  g_vh [ROWS*DD], g_vl[ROWS*DD];
__device__ bf16  g_oh [ROWS*DD], g_ol[ROWS*DD];
__device__ float g_x1 [ROWS*DD];
__device__ bf16  g_h2h[ROWS*DD], g_h2l[ROWS*DD];
__device__ bf16  g_t1h[ROWS*RF], g_t1l[ROWS*RF];
__device__ bf16  g_gh [ROWS*DFF], g_gl[ROWS*DFF];
__device__ bf16  g_t2h[ROWS*RF], g_t2l[ROWS*RF];

__device__ __forceinline__ void bsplit(float a, bf16& h, bf16& l) {
    h = __float2bfloat16(a);
    l = __float2bfloat16(a - __bfloat162float(h));
}
__device__ __forceinline__ unsigned pack2(bf16 a, bf16 b) {
    __nv_bfloat162 t(a, b);
    return *(unsigned*)&t;
}
__device__ __forceinline__ float gelu_t(float x) {
    float t = 0.7978845608028654f * (x + 0.044715f * x * x * x);
    return 0.5f * x * (1.0f + tanhf(t));
}

// ---------------- layernorm row body (shared by ln_split + preproc) ----------------
__device__ __forceinline__ void ln_row(const float* __restrict__ x,
                                       const float* __restrict__ w,
                                       const float* __restrict__ b,
                                       bf16* __restrict__ oh,
                                       bf16* __restrict__ ol,
                                       int row, int tid) {
    const float* xr = x + (size_t)row * DD;
    float vals[3];
    float s = 0.f, s2 = 0.f;
#pragma unroll
    for (int i = 0; i < 3; i++) {
        float v = xr[tid + i * 256];
        vals[i] = v; s += v; s2 += v * v;
    }
#pragma unroll
    for (int off = 16; off > 0; off >>= 1) {
        s  += __shfl_xor_sync(0xffffffffu, s,  off);
        s2 += __shfl_xor_sync(0xffffffffu, s2, off);
    }
    __shared__ float sh[8], sh2[8];
    int warp = tid >> 5, lane = tid & 31;
    if (lane == 0) { sh[warp] = s; sh2[warp] = s2; }
    __syncthreads();
    float ts = 0.f, ts2 = 0.f;
#pragma unroll
    for (int i = 0; i < 8; i++) { ts += sh[i]; ts2 += sh2[i]; }
    float mean = ts * (1.0f / DD);
    float var  = ts2 * (1.0f / DD) - mean * mean;
    float rstd = rsqrtf(var + 1e-6f);
#pragma unroll
    for (int i = 0; i < 3; i++) {
        int c = tid + i * 256;
        float y = (vals[i] - mean) * rstd * w[c] + b[c];
        bsplit(y, oh[(size_t)row * DD + c], ol[(size_t)row * DD + c]);
    }
}

__global__ __launch_bounds__(256) void ln_split(const float* __restrict__ x,
                                                const float* __restrict__ w,
                                                const float* __restrict__ b,
                                                bf16* __restrict__ oh,
                                                bf16* __restrict__ ol) {
    ln_row(x, w, b, oh, ol, blockIdx.x, threadIdx.x);
}

// ---------------- fused preprocessing: LN1 + weff + all weight splits ----------------
#define N_WOT (DD*DD)
#define N_UI  (DD*RF)
#define N_VI  (RF*2*DFF)
#define N_UO  (DFF*RF)
#define N_VO  (RF*DD)
#define N_ALL (N_WOT+N_UI+N_VI+N_UO+N_VO)
#define NB_LN   ROWS                       // 8192
#define NB_WEFF ((3*DD*DD + 255)/256)      // 6912
#define NB_SPL  ((N_ALL + 255)/256)        // 23808
#define NB_PRE  (NB_LN + NB_WEFF + NB_SPL)
__global__ __launch_bounds__(256) void preproc(
    const float* __restrict__ x, const float* __restrict__ anw, const float* __restrict__ anb,
    bf16* __restrict__ hh, bf16* __restrict__ hl,
    const float* __restrict__ Uq, const float* __restrict__ Vq,
    const float* __restrict__ Uk, const float* __restrict__ Vk,
    const float* __restrict__ Uv, const float* __restrict__ Vv,
    bf16* __restrict__ wh, bf16* __restrict__ wl,
    const float* __restrict__ Wo, const float* __restrict__ Ui, const float* __restrict__ Vi,
    const float* __restrict__ Uo, const float* __restrict__ Vo,
    bf16* __restrict__ woth, bf16* __restrict__ wotl,
    bf16* __restrict__ uih,  bf16* __restrict__ uil,
    bf16* __restrict__ vih,  bf16* __restrict__ vil,
    bf16* __restrict__ uoh,  bf16* __restrict__ uol,
    bf16* __restrict__ voh,  bf16* __restrict__ vol)
{
    int blk = blockIdx.x;
    int tid = threadIdx.x;
    if (blk < NB_LN) {
        ln_row(x, anw, anb, hh, hl, blk, tid);
        return;
    }
    blk -= NB_LN;
    if (blk < NB_WEFF) {
        int idx = blk * 256 + tid;
        if (idx >= 3 * DD * DD) return;
        int which = idx / (DD * DD);
        int rem = idx % (DD * DD);
        int d = rem / DD, j = rem % DD;
        int hhd = j >> 6, e = j & 63;
        const float* U = (which == 0) ? Uq : (which == 1) ? Uk : Uv;
        const float* V = (which == 0) ? Vq : (which == 1) ? Vk : Vv;
        const float* Uhd = U + ((size_t)hhd * DD + d) * RA;
        const float* Vh  = V + (size_t)hhd * RA * HDD + e;
        float acc = 0.f;
#pragma unroll
        for (int r = 0; r < RA; r++) acc += Uhd[r] * Vh[r * HDD];
        bsplit(acc, wh[idx], wl[idx]);
        return;
    }
    blk -= NB_WEFF;
    int idx = blk * 256 + tid;
    if (idx >= N_ALL) return;
    if (idx < N_WOT) {
        int k = idx / DD, n = idx % DD;
        bsplit(Wo[(size_t)n * DD + k], woth[idx], wotl[idx]);
        return;
    }
    idx -= N_WOT;
    if (idx < N_UI) { bsplit(Ui[idx], uih[idx], uil[idx]); return; }
    idx -= N_UI;
    if (idx < N_VI) {
        int k = idx / (2 * DFF), n = idx % (2 * DFF);
        int j = n >> 1;
        int srcn = (n & 1) ? (DFF + j) : j;
        bsplit(Vi[(size_t)k * (2 * DFF) + srcn], vih[idx], vil[idx]);
        return;
    }
    idx -= N_VI;
    if (idx < N_UO) { bsplit(Uo[idx], uoh[idx], uol[idx]); return; }
    idx -= N_UO;
    bsplit(Vo[idx], voh[idx], vol[idx]);
}

// ---------------- shared GEMM mainloop (3-stage, single barrier, R14-proven) ----------------
struct GemmCore {
    wmma::fragment<wmma::accumulator, 16, 16, 16, float> cf[4][2];
};

__device__ __forceinline__ void gemm_mainloop(
    GemmCore& gc, bf16* smb, int tid, int warp_m, int warp_n,
    const bf16* Agh, const bf16* Agl, const bf16* Bgh, const bf16* Bgl,
    int m0, int n0, int N, int K)
{
    auto issue = [&](int c, int st) {
        int k0 = c * BK;
        bf16* sAh = smb + st * STAGE;
        bf16* sAl = sAh + A_TILE;
        bf16* sBh = sAl + A_TILE;
        bf16* sBl = sBh + B_TILE;
#pragma unroll
        for (int i = 0; i < 2; i++) {
            int t = tid + i * 256;
            int ar = t >> 2;
            int ac = (t & 3) * 8;
            size_t ag = (size_t)(m0 + ar) * K + k0 + ac;
            __pipeline_memcpy_async(&sAh[ar * LDAs + ac], &Agh[ag], 16);
            __pipeline_memcpy_async(&sAl[ar * LDAs + ac], &Agl[ag], 16);
            int br = t >> 4;
            int bc = (t & 15) * 8;
            size_t bg = (size_t)(k0 + br) * N + n0 + bc;
            __pipeline_memcpy_async(&sBh[br * LDBs + bc], &Bgh[bg], 16);
            __pipeline_memcpy_async(&sBl[br * LDBs + bc], &Bgl[bg], 16);
        }
    };

#pragma unroll
    for (int i = 0; i < 4; i++)
#pragma unroll
        for (int j = 0; j < 2; j++) wmma::fill_fragment(gc.cf[i][j], 0.0f);

    int nch = K / BK;
    issue(0, 0); __pipeline_commit();
    issue(1, 1); __pipeline_commit();

    int st = 0;
    int stn = 2;
    for (int c = 0; c < nch; c++) {
        __pipeline_wait_prior(1);
        __syncthreads();
        bf16* sAh = smb + st * STAGE;
        bf16* sAl = sAh + A_TILE;
        bf16* sBh = sAl + A_TILE;
        bf16* sBl = sBh + B_TILE;
#pragma unroll
        for (int ks = 0; ks < 2; ks++) {
            wmma::fragment<wmma::matrix_b, 16, 16, 16, bf16, wmma::row_major> bh[2], bl[2];
#pragma unroll
            for (int j = 0; j < 2; j++) {
                wmma::load_matrix_sync(bh[j], &sBh[(ks * 16) * LDBs + warp_n * 32 + j * 16], LDBs);
                wmma::load_matrix_sync(bl[j], &sBl[(ks * 16) * LDBs + warp_n * 32 + j * 16], LDBs);
            }
#pragma unroll
            for (int i = 0; i < 4; i++) {
                wmma::fragment<wmma::matrix_a, 16, 16, 16, bf16, wmma::row_major> ah, al;
                wmma::load_matrix_sync(ah, &sAh[(warp_m * 64 + i * 16) * LDAs + ks * 16], LDAs);
                wmma::load_matrix_sync(al, &sAl[(warp_m * 64 + i * 16) * LDAs + ks * 16], LDAs);
#pragma unroll
                for (int j = 0; j < 2; j++) {
                    wmma::mma_sync(gc.cf[i][j], ah, bh[j], gc.cf[i][j]);
                    wmma::mma_sync(gc.cf[i][j], ah, bl[j], gc.cf[i][j]);
                    wmma::mma_sync(gc.cf[i][j], al, bh[j], gc.cf[i][j]);
                }
            }
        }
        if (c + 2 < nch) issue(c + 2, stn);
        __pipeline_commit();
        st  = (st  == 2) ? 0 : st + 1;
        stn = (stn == 2) ? 0 : stn + 1;
    }
    __syncthreads();
}

__device__ __forceinline__ void gemm_store_frags(GemmCore& gc, float* Csm, int warp_m, int warp_n) {
#pragma unroll
    for (int i = 0; i < 4; i++)
#pragma unroll
        for (int j = 0; j < 2; j++)
            wmma::store_matrix_sync(&Csm[(warp_m * 64 + i * 16) * LDC + warp_n * 32 + j * 16],
                                    gc.cf[i][j], LDC, wmma::mem_row_major);
}

// ---------------- fused QKV GEMM (z: 0=Q rope*0.125, 1=K rope*1, 2=V split scatter) ----------------
__global__ __launch_bounds__(256, 2) void gemm_qkv(
    const bf16* __restrict__ Agh, const bf16* __restrict__ Agl,
    const bf16* __restrict__ Wh, const bf16* __restrict__ Wl,
    const float* __restrict__ bq, const float* __restrict__ bk, const float* __restrict__ bv,
    const float* __restrict__ cosT, const float* __restrict__ sinT,
    bf16* __restrict__ Qh, bf16* __restrict__ Ql,
    bf16* __restrict__ Kh, bf16* __restrict__ Kl,
    bf16* __restrict__ Vh, bf16* __restrict__ Vl)
{
    extern __shared__ __align__(16) char smraw[];
    bf16* smb = (bf16*)smraw;
    int tid = threadIdx.x;
    int wid = tid >> 5;
    int warp_m = wid >> 2, warp_n = wid & 3;
    int m0 = blockIdx.y * 128, n0 = blockIdx.x * 128;
    int z = blockIdx.z;

    const bf16* Bgh = Wh + (size_t)z * DD * DD;
    const bf16* Bgl = Wl + (size_t)z * DD * DD;
    const float* bias = (z == 0) ? bq : (z == 1) ? bk : bv;
    float scale = (z == 0) ? 0.125f : 1.0f;

    GemmCore gc;
    gemm_mainloop(gc, smb, tid, warp_m, warp_n, Agh, Agl, Bgh, Bgl, m0, n0, DD, DD);

    float* Csm = (float*)smraw;
    gemm_store_frags(gc, Csm, warp_m, warp_n);
    __syncthreads();

#pragma unroll
    for (int it = 0; it < 16; it++) {
        int idx = tid + it * 256;
        int r = idx >> 5;
        int c4 = (idx & 31) << 2;
        float4 v = *(const float4*)&Csm[r * LDC + c4];
        int m = m0 + r, n = n0 + c4;
        int e = n & 63;
        int s = m & 2047;
        int b = m >> 11, head = n >> 6;
        size_t o = (((size_t)b * HH + head) * SS + s) * HDD + e;
        if (z == 2) {
            float4 bb = *(const float4*)&bias[n];
            v.x += bb.x; v.y += bb.y; v.z += bb.z; v.w += bb.w;
            bf16 hv[4], lv[4];
            bsplit(v.x, hv[0], lv[0]); bsplit(v.y, hv[1], lv[1]);
            bsplit(v.z, hv[2], lv[2]); bsplit(v.w, hv[3], lv[3]);
            *(uint2*)&Vh[o] = *(uint2*)hv;
            *(uint2*)&Vl[o] = *(uint2*)lv;
        } else {
            float4 p = *(const float4*)&Csm[r * LDC + (c4 ^ 32)];
            float4 bb = *(const float4*)&bias[n];
            v.x += bb.x; v.y += bb.y; v.z += bb.z; v.w += bb.w;
            float4 pb = *(const float4*)&bias[n ^ 32];
            p.x += pb.x; p.y += pb.y; p.z += pb.z; p.w += pb.w;
            float4 cs = *(const float4*)&cosT[s * HDD + e];
            float4 sn = *(const float4*)&sinT[s * HDD + e];
            float4 o4;
            if (e < 32) {
                o4.x = v.x * cs.x - p.x * sn.x; o4.y = v.y * cs.y - p.y * sn.y;
                o4.z = v.z * cs.z - p.z * sn.z; o4.w = v.w * cs.w - p.w * sn.w;
            } else {
                o4.x = v.x * cs.x + p.x * sn.x; o4.y = v.y * cs.y + p.y * sn.y;
                o4.z = v.z * cs.z + p.z * sn.z; o4.w = v.w * cs.w + p.w * sn.w;
            }
            o4.x *= scale; o4.y *= scale; o4.z *= scale; o4.w *= scale;
            bf16* Ch = (z == 0) ? Qh : Kh;
            bf16* Cl = (z == 0) ? Ql : Kl;
            bf16 hv[4], lv[4];
            bsplit(o4.x, hv[0], lv[0]); bsplit(o4.y, hv[1], lv[1]);
            bsplit(o4.z, hv[2], lv[2]); bsplit(o4.w, hv[3], lv[3]);
            *(uint2*)&Ch[o] = *(uint2*)hv;
            *(uint2*)&Cl[o] = *(uint2*)lv;
        }
    }
}

// ---------------- generic bf16x3 GEMM (OUTMODE: 0 fp32+bias+res; 2 split; 4 GEGLU) ----------------
template<int OUTMODE>
__global__ __launch_bounds__(256, 2) void gemm_bf3(
    const bf16* __restrict__ Agh, const bf16* __restrict__ Agl,
    const bf16* __restrict__ Bgh, const bf16* __restrict__ Bgl,
    const float* __restrict__ bias, const float* __restrict__ res,
    float* __restrict__ C, bf16* __restrict__ Ch, bf16* __restrict__ Cl,
    int M, int N, int K)
{
    extern __shared__ __align__(16) char smraw[];
    bf16* smb = (bf16*)smraw;
    int tid = threadIdx.x;
    int wid = tid >> 5;
    int warp_m = wid >> 2, warp_n = wid & 3;
    int m0 = blockIdx.y * 128, n0 = blockIdx.x * 128;

    GemmCore gc;
    gemm_mainloop(gc, smb, tid, warp_m, warp_n, Agh, Agl, Bgh, Bgl, m0, n0, N, K);

    float* Csm = (float*)smraw;
    gemm_store_frags(gc, Csm, warp_m, warp_n);
    __syncthreads();

#pragma unroll
    for (int it = 0; it < 16; it++) {
        int idx = tid + it * 256;
        int r = idx >> 5;
        int c4 = (idx & 31) << 2;
        float4 v = *(const float4*)&Csm[r * LDC + c4];
        int m = m0 + r, n = n0 + c4;
        if (OUTMODE != 4) {
            if (bias) {
                float4 bb = *(const float4*)&bias[n];
                v.x += bb.x; v.y += bb.y; v.z += bb.z; v.w += bb.w;
            }
            if (res) {
                float4 rr = *(const float4*)&res[(size_t)m * N + n];
                v.x += rr.x; v.y += rr.y; v.z += rr.z; v.w += rr.w;
            }
        }
        if (OUTMODE == 0) {
            *(float4*)&C[(size_t)m * N + n] = v;
        } else if (OUTMODE == 2) {
            bf16 hv[4], lv[4];
            bsplit(v.x, hv[0], lv[0]); bsplit(v.y, hv[1], lv[1]);
            bsplit(v.z, hv[2], lv[2]); bsplit(v.w, hv[3], lv[3]);
            *(uint2*)&Ch[(size_t)m * N + n] = *(uint2*)hv;
            *(uint2*)&Cl[(size_t)m * N + n] = *(uint2*)lv;
        } else {  // OUTMODE == 4
            int j0 = n >> 1;
            float g1a = v.x + bias[j0];
            float g2a = v.y + bias[DFF + j0];
            float g1b = v.z + bias[j0 + 1];
            float g2b = v.w + bias[DFF + j0 + 1];
            float ga = gelu_t(g1a) * g2a;
            float gb = gelu_t(g1b) * g2b;
            bf16 h0, l0, h1, l1;
            bsplit(ga, h0, l0); bsplit(gb, h1, l1);
            size_t o = (size_t)m * DFF + j0;
            *(unsigned*)&Ch[o] = pack2(h0, h1);
            *(unsigned*)&Cl[o] = pack2(l0, l1);
        }
    }
}

// ---------------- tensor-core flash attention (max-free, 3-term P*V, warp-local sync) ----------------
#define LDQ 72
#define LDKV 72
#define LDP 72
#define LDSS 68
#define ATT_KV_STAGE (4*64*LDKV)
#define ATT_SMEM 182272
__global__ __launch_bounds__(256, 1) void attn_tc(
    const bf16* __restrict__ Qh_, const bf16* __restrict__ Ql_,
    const bf16* __restrict__ Kh_, const bf16* __restrict__ Kl_,
    const bf16* __restrict__ Vh_, const bf16* __restrict__ Vl_,
    bf16* __restrict__ Oh_, bf16* __restrict__ Ol_)
{
    extern __shared__ __align__(16) char smraw_[];
    bf16* sQh = (bf16*)smraw_;
    bf16* sQl = sQh + 128 * LDQ;
    bf16* sKV = sQl + 128 * LDQ;
    bf16* sPh = sKV + 2 * ATT_KV_STAGE;
    bf16* sPl = sPh + 128 * LDP;
    float* sS = (float*)(sPl + 128 * LDP);

    int tid = threadIdx.x;
    int warp = tid >> 5;
    int bh = blockIdx.y;
    int q0 = blockIdx.x * 128;
    size_t qoff = ((size_t)bh * SS + q0) * HDD;
    size_t bhoff = (size_t)bh * SS * HDD;

#pragma unroll
    for (int i = 0; i < 4; i++) {
        int idx = tid + i * 256;
        int r = idx >> 3, c8 = (idx & 7) * 8;
        *(uint4*)&sQh[r * LDQ + c8] = *(const uint4*)&Qh_[qoff + (size_t)r * HDD + c8];
        *(uint4*)&sQl[r * LDQ + c8] = *(const uint4*)&Ql_[qoff + (size_t)r * HDD + c8];
    }

    auto kv_issue = [&](int it, int st) {
        size_t koff = bhoff + (size_t)(it * 64) * HDD;
        bf16* kh = sKV + st * ATT_KV_STAGE;
        bf16* kl = kh + 64 * LDKV;
        bf16* vh = kl + 64 * LDKV;
        bf16* vl = vh + 64 * LDKV;
#pragma unroll
        for (int i = 0; i < 2; i++) {
            int idx = tid + i * 256;
            int rr = idx >> 3, c8 = (idx & 7) * 8;
            size_t g = koff + (size_t)rr * HDD + c8;
            __pipeline_memcpy_async(&kh[rr * LDKV + c8], &Kh_[g], 16);
            __pipeline_memcpy_async(&kl[rr * LDKV + c8], &Kl_[g], 16);
            __pipeline_memcpy_async(&vh[rr * LDKV + c8], &Vh_[g], 16);
            __pipeline_memcpy_async(&vl[rr * LDKV + c8], &Vl_[g], 16);
        }
        __pipeline_commit();
    };

    kv_issue(0, 0);
    kv_issue(1, 1);

    wmma::fragment<wmma::accumulator, 16, 16, 16, float> of[4];
#pragma unroll
    for (int j = 0; j < 4; j++) wmma::fill_fragment(of[j], 0.f);

    float l = 0.f;
    int r = tid >> 1, c0 = (tid & 1) * 32;
    const int niter = SS / 64;

    for (int it = 0; it < niter; it++) {
        int st = it & 1;
        __pipeline_wait_prior(1);
        __syncthreads();                 // cross-warp visibility of KV stage
        bf16* kh = sKV + st * ATT_KV_STAGE;
        bf16* kl = kh + 64 * LDKV;
        bf16* vh = kl + 64 * LDKV;
        bf16* vl = vh + 64 * LDKV;

        // ---- S = Qh*Kh + Qh*Kl + Ql*Kh ----
        {
            wmma::fragment<wmma::accumulator, 16, 16, 16, float> sf[4];
#pragma unroll
            for (int j = 0; j < 4; j++) wmma::fill_fragment(sf[j], 0.f);
#pragma unroll
            for (int ks = 0; ks < 4; ks++) {
                wmma::fragment<wmma::matrix_a, 16, 16, 16, bf16, wmma::row_major> ah, al;
                wmma::load_matrix_sync(ah, &sQh[(warp * 16) * LDQ + ks * 16], LDQ);
                wmma::load_matrix_sync(al, &sQl[(warp * 16) * LDQ + ks * 16], LDQ);
#pragma unroll
                for (int j = 0; j < 4; j++) {
                    wmma::fragment<wmma::matrix_b, 16, 16, 16, bf16, wmma::col_major> bhf, blf;
                    wmma::load_matrix_sync(bhf, &kh[(j * 16) * LDKV + ks * 16], LDKV);
                    wmma::load_matrix_sync(blf, &kl[(j * 16) * LDKV + ks * 16], LDKV);
                    wmma::mma_sync(sf[j], ah, bhf, sf[j]);
                    wmma::mma_sync(sf[j], ah, blf, sf[j]);
                    wmma::mma_sync(sf[j], al, bhf, sf[j]);
                }
            }
#pragma unroll
            for (int j = 0; j < 4; j++)
                wmma::store_matrix_sync(&sS[(warp * 16) * LDSS + j * 16], sf[j], LDSS, wmma::mem_row_major);
        }
        __syncwarp();    // S rows [16w,16w+16) are warp-local

        // ---- max-free softmax (warp-local rows) ----
        {
            const float* srow = sS + r * LDSS + c0;
            unsigned* ph = (unsigned*)&sPh[r * LDP + c0];
            unsigned* pl = (unsigned*)&sPl[r * LDP + c0];
            float sum = 0.f;
#pragma unroll
            for (int cc = 0; cc < 8; cc++) {
                float4 sv = *(const float4*)&srow[cc * 4];
                float p0 = __expf(sv.x), p1 = __expf(sv.y);
                float p2 = __expf(sv.z), p3 = __expf(sv.w);
                sum += (p0 + p1) + (p2 + p3);
                bf16 h0, l0, h1, l1, h2, l2, h3, l3;
                bsplit(p0, h0, l0); bsplit(p1, h1, l1);
                bsplit(p2, h2, l2); bsplit(p3, h3, l3);
                uint2 uh = { pack2(h0, h1), pack2(h2, h3) };
                uint2 ul = { pack2(l0, l1), pack2(l2, l3) };
                *(uint2*)&ph[cc * 2] = uh;
                *(uint2*)&pl[cc * 2] = ul;
            }
            l += sum;
        }
        __syncwarp();    // P rows [16w,16w+16) are warp-local

        // ---- of += Ph*Vh + Pl*Vh + Ph*Vl ----
        {
            wmma::fragment<wmma::matrix_a, 16, 16, 16, bf16, wmma::row_major> pah[4], pal[4];
#pragma unroll
            for (int ks = 0; ks < 4; ks++) {
                wmma::load_matrix_sync(pah[ks], &sPh[(warp * 16) * LDP + ks * 16], LDP);
                wmma::load_matrix_sync(pal[ks], &sPl[(warp * 16) * LDP + ks * 16], LDP);
            }
#pragma unroll
            for (int j = 0; j < 4; j++) {
#pragma unroll
                for (int ks = 0; ks < 4; ks++) {
                    wmma::fragment<wmma::matrix_b, 16, 16, 16, bf16, wmma::row_major> vbh, vbl;
                    wmma::load_matrix_sync(vbh, &vh[(ks * 16) * LDKV + j * 16], LDKV);
                    wmma::load_matrix_sync(vbl, &vl[(ks * 16) * LDKV + j * 16], LDKV);
                    wmma::mma_sync(of[j], pah[ks], vbh, of[j]);
                    wmma::mma_sync(of[j], pal[ks], vbh, of[j]);
                    wmma::mma_sync(of[j], pah[ks], vbl, of[j]);
                }
            }
        }
        __syncthreads();   // all warps done reading KV stage st before refill

        if (it + 2 < niter) kv_issue(it + 2, st);
        else __pipeline_commit();
    }

    l += __shfl_xor_sync(0xffffffffu, l, 1);
#pragma unroll
    for (int j = 0; j < 4; j++)
        wmma::store_matrix_sync(&sS[(warp * 16) * LDSS + j * 16], of[j], LDSS, wmma::mem_row_major);
    __syncwarp();         // O rows warp-local

    int b = bh / HH, hd = bh % HH;
    float inv = 1.0f / l;
    size_t obase = ((size_t)(b * SS + q0 + r)) * DD + hd * HDD + c0;
    const float* orow = sS + r * LDSS + c0;
#pragma unroll
    for (int cc = 0; cc < 8; cc++) {
        float4 ov = *(const float4*)&orow[cc * 4];
        bf16 h0, l0, h1, l1, h2, l2, h3, l3;
        bsplit(ov.x * inv, h0, l0); bsplit(ov.y * inv, h1, l1);
        bsplit(ov.z * inv, h2, l2); bsplit(ov.w * inv, h3, l3);
        uint2 uh = { pack2(h0, h1), pack2(h2, h3) };
        uint2 ul = { pack2(l0, l1), pack2(l2, l3) };
        *(uint2*)&Oh_[obase + cc * 4] = uh;
        *(uint2*)&Ol_[obase + cc * 4] = ul;
    }
}

// ---------------- launch ----------------
extern "C" void kernel_launch(void* const* d_in, const int* in_sizes, int n_in,
                              void* d_out, int out_size) {
    const float* x    = (const float*)d_in[0];
    const float* anw  = (const float*)d_in[1];
    const float* anb  = (const float*)d_in[2];
    const float* Uq   = (const float*)d_in[3];
    const float* Vq   = (const float*)d_in[4];
    const float* bq   = (const float*)d_in[5];
    const float* Uk   = (const float*)d_in[6];
    const float* Vk   = (const float*)d_in[7];
    const float* bk   = (const float*)d_in[8];
    const float* Uv   = (const float*)d_in[9];
    const float* Vv   = (const float*)d_in[10];
    const float* bv   = (const float*)d_in[11];
    const float* Wo_w = (const float*)d_in[12];
    const float* Wo_b = (const float*)d_in[13];
    const float* mnw  = (const float*)d_in[14];
    const float* mnb  = (const float*)d_in[15];
    const float* Ui   = (const float*)d_in[16];
    const float* Vi   = (const float*)d_in[17];
    const float* bi   = (const float*)d_in[18];
    const float* Uo   = (const float*)d_in[19];
    const float* Vo   = (const float*)d_in[20];
    const float* bo   = (const float*)d_in[21];
    const float* cosT = (const float*)d_in[22];
    const float* sinT = (const float*)d_in[23];
    float* out = (float*)d_out;

    bf16 *hh,*hl,*weffh,*weffl,*woth,*wotl,*uih,*uil,*vih,*vil,*uoh,*uol,*voh,*vol;
    bf16 *qh,*ql,*kh,*kl,*vh,*vl,*oh,*ol,*h2h,*h2l,*t1h,*t1l,*gh,*gl,*t2h,*t2l;
    float *x1;
    cudaGetSymbolAddress((void**)&hh, g_hh);   cudaGetSymbolAddress((void**)&hl, g_hl);
    cudaGetSymbolAddress((void**)&weffh, g_weffh); cudaGetSymbolAddress((void**)&weffl, g_weffl);
    cudaGetSymbolAddress((void**)&woth, g_woth);   cudaGetSymbolAddress((void**)&wotl, g_wotl);
    cudaGetSymbolAddress((void**)&uih, g_uih); cudaGetSymbolAddress((void**)&uil, g_uil);
    cudaGetSymbolAddress((void**)&vih, g_vih); cudaGetSymbolAddress((void**)&vil, g_vil);
    cudaGetSymbolAddress((void**)&uoh, g_uoh); cudaGetSymbolAddress((void**)&uol, g_uol);
    cudaGetSymbolAddress((void**)&voh, g_voh); cudaGetSymbolAddress((void**)&vol, g_vol);
    cudaGetSymbolAddress((void**)&qh, g_qh); cudaGetSymbolAddress((void**)&ql, g_ql);
    cudaGetSymbolAddress((void**)&kh, g_kh); cudaGetSymbolAddress((void**)&kl, g_kl);
    cudaGetSymbolAddress((void**)&vh, g_vh); cudaGetSymbolAddress((void**)&vl, g_vl);
    cudaGetSymbolAddress((void**)&oh, g_oh); cudaGetSymbolAddress((void**)&ol, g_ol);
    cudaGetSymbolAddress((void**)&x1, g_x1);
    cudaGetSymbolAddress((void**)&h2h, g_h2h); cudaGetSymbolAddress((void**)&h2l, g_h2l);
    cudaGetSymbolAddress((void**)&t1h, g_t1h); cudaGetSymbolAddress((void**)&t1l, g_t1l);
    cudaGetSymbolAddress((void**)&gh, g_gh); cudaGetSymbolAddress((void**)&gl, g_gl);
    cudaGetSymbolAddress((void**)&t2h, g_t2h); cudaGetSymbolAddress((void**)&t2l, g_t2l);

    cudaFuncSetAttribute(attn_tc, cudaFuncAttributeMaxDynamicSharedMemorySize, ATT_SMEM);
    cudaFuncSetAttribute(gemm_qkv,   cudaFuncAttributeMaxDynamicSharedMemorySize, GEMM_SMEM);
    cudaFuncSetAttribute(gemm_bf3<0>, cudaFuncAttributeMaxDynamicSharedMemorySize, GEMM_SMEM);
    cudaFuncSetAttribute(gemm_bf3<2>, cudaFuncAttributeMaxDynamicSharedMemorySize, GEMM_SMEM);
    cudaFuncSetAttribute(gemm_bf3<4>, cudaFuncAttributeMaxDynamicSharedMemorySize, GEMM_SMEM);

    // 1. fused preprocessing: LN1 + weff + all weight splits (one launch)
    preproc<<<NB_PRE, 256>>>(x, anw, anb, hh, hl,
                             Uq, Vq, Uk, Vk, Uv, Vv, weffh, weffl,
                             Wo_w, Ui, Vi, Uo, Vo,
                             woth, wotl, uih, uil, vih, vil, uoh, uol, voh, vol);
    // 2. fused Q/K/V projections (one launch)
    gemm_qkv<<<dim3(DD / 128, ROWS / 128, 3), 256, GEMM_SMEM>>>(
        hh, hl, weffh, weffl, bq, bk, bv, cosT, sinT, qh, ql, kh, kl, vh, vl);
    // 3. tensor-core attention
    attn_tc<<<dim3(SS / 128, BB * HH), 256, ATT_SMEM>>>(qh, ql, kh, kl, vh, vl, oh, ol);
    // 4. x1 = x + o @ Wo^T + Wo_b
    gemm_bf3<0><<<dim3(DD / 128, ROWS / 128), 256, GEMM_SMEM>>>(oh, ol, woth, wotl, Wo_b, x, x1, nullptr, nullptr, ROWS, DD, DD);
    // 5. LN2
    ln_split<<<ROWS, 256>>>(x1, mnw, mnb, h2h, h2l);
    // 6. t1 = h2 @ Ui
    gemm_bf3<2><<<dim3(RF / 128, ROWS / 128), 256, GEMM_SMEM>>>(h2h, h2l, uih, uil, nullptr, nullptr, nullptr, t1h, t1l, ROWS, RF, DD);
    // 7. g = GEGLU(t1 @ ViP + biP) fused
    gemm_bf3<4><<<dim3(2 * DFF / 128, ROWS / 128), 256, GEMM_SMEM>>>(t1h, t1l, vih, vil, bi, nullptr, nullptr, gh, gl, ROWS, 2 * DFF, RF);
    // 8. t2 = g @ Uo
    gemm_bf3<2><<<dim3(RF / 128, ROWS / 128), 256, GEMM_SMEM>>>(gh, gl, uoh, uol, nullptr, nullptr, nullptr, t2h, t2l, ROWS, RF, DFF);
    // 9. out = x1 + t2 @ Vo + bo
    gemm_bf3<0><<<dim3(DD / 128, ROWS / 128), 256, GEMM_SMEM>>>(t2h, t2l, voh, vol, bo, x1, out, nullptr, nullptr, ROWS, DD, RF);
}